// round 12
// baseline (speedup 1.0000x reference)
#include <cuda_runtime.h>
#include <cuda_bf16.h>
#include <cstdint>

#define N_NODES 50000
#define N_EDGES 600000
#define N_GRAPHS 2000
#define IN_FEATS 64
#define HIDDEN 128
#define SCAN_BS 1024
#define SCAN_NB ((N_NODES + SCAN_BS - 1) / SCAN_BS)   // 49
#define PRE_NB 98

typedef unsigned long long u64;

// ---------------- scratch (device globals; no allocation allowed) ----------
__device__ int   g_deg_out[N_NODES];
__device__ int   g_deg_in[N_NODES];
__device__ float g_cout[N_NODES];
__device__ float g_cin[N_NODES];
__device__ int   g_rowstart[N_NODES + 1];
__device__ int   g_fill[N_NODES];
__device__ int   g_scanagg[SCAN_NB];
__device__ int   g_scanflag[SCAN_NB];
__device__ int   g_csr_src[N_EDGES];
__device__ int   g_gstart[N_GRAPHS + 1];
__device__ int   g_bar_cnt;
__device__ int   g_bar_gen;
__device__ __nv_bfloat16 g_agg16[(size_t)N_NODES * HIDDEN];  // pull output (bf16)
__device__ __nv_bfloat16 g_f16[(size_t)N_NODES * IN_FEATS];  // feats * c_out
__device__ __nv_bfloat16 g_x16[(size_t)N_NODES * HIDDEN];    // layer1 out * c_out
__device__ __nv_bfloat16 g_y16[(size_t)N_NODES * HIDDEN];    // layer2 out * c_out
__device__ float g_y3f[(size_t)N_NODES * HIDDEN];            // layer3 out (fp32)
__device__ float g_gsum[(size_t)N_GRAPHS * HIDDEN];          // per-graph MEAN

// ---------------- helpers ---------------------------------------------------
__device__ __forceinline__ void mma_bf16(float& d0, float& d1, float& d2, float& d3,
                                         uint32_t a0, uint32_t a1, uint32_t a2, uint32_t a3,
                                         uint32_t b0, uint32_t b1) {
    asm volatile(
        "mma.sync.aligned.m16n8k16.row.col.f32.bf16.bf16.f32 "
        "{%0,%1,%2,%3}, {%4,%5,%6,%7}, {%8,%9}, {%0,%1,%2,%3};"
        : "+f"(d0), "+f"(d1), "+f"(d2), "+f"(d3)
        : "r"(a0), "r"(a1), "r"(a2), "r"(a3), "r"(b0), "r"(b1));
}
__device__ __forceinline__ uint32_t f2bf2(float lo, float hi) {
    __nv_bfloat162 h = __floats2bfloat162_rn(lo, hi);
    return *reinterpret_cast<uint32_t*>(&h);
}
__device__ __forceinline__ uint32_t hadd2u(uint32_t a, uint32_t b) {
    __nv_bfloat162 ha = *reinterpret_cast<__nv_bfloat162*>(&a);
    __nv_bfloat162 hb = *reinterpret_cast<__nv_bfloat162*>(&b);
    __nv_bfloat162 r = __hadd2(ha, hb);
    return *reinterpret_cast<uint32_t*>(&r);
}
__device__ __forceinline__ void acc_f32x2(u64& acc, uint32_t p) {
    asm("{\n\t"
        ".reg .b32 lo, hi;\n\t"
        ".reg .b64 v;\n\t"
        "shl.b32 lo, %1, 16;\n\t"
        "and.b32 hi, %1, 0xFFFF0000;\n\t"
        "mov.b64 v, {lo, hi};\n\t"
        "add.rn.f32x2 %0, %0, v;\n\t"
        "}" : "+l"(acc) : "r"(p));
}
__device__ __forceinline__ float2 unpack_f32x2(u64 v) {
    float2 f; asm("mov.b64 {%0, %1}, %2;" : "=f"(f.x), "=f"(f.y) : "l"(v)); return f;
}

// software grid barrier (all 98 blocks co-resident on 148 SMs)
__device__ __forceinline__ void grid_bar(int nb) {
    __syncthreads();
    if (threadIdx.x == 0) {
        int gen = atomicAdd(&g_bar_gen, 0);
        __threadfence();
        int arrived = atomicAdd(&g_bar_cnt, 1) + 1;
        if (arrived == nb) {
            g_bar_cnt = 0;
            __threadfence();
            atomicAdd(&g_bar_gen, 1);
        } else {
            while (atomicAdd(&g_bar_gen, 0) == gen) {}
        }
        __threadfence();
    }
    __syncthreads();
}

// ---------------- fused prepass: zero -> degree -> scan/coeff -> fill+feats ---
__global__ __launch_bounds__(SCAN_BS)
void prepass_kernel(const int* __restrict__ src, const int* __restrict__ dst,
                    const int* __restrict__ gid, const float* __restrict__ feats) {
    const int NT = gridDim.x * blockDim.x;
    const int t = blockIdx.x * blockDim.x + threadIdx.x;

    // ---- P0: zero + graph segment boundaries (gid is sorted) ----
    for (int i = t; i < N_NODES; i += NT) { g_deg_out[i] = 0; g_deg_in[i] = 0; }
    for (int i = t; i < SCAN_NB; i += NT) g_scanflag[i] = 0;
    for (int i = t; i < N_NODES; i += NT) {
        int gi = __ldg(&gid[i]);
        int gp = (i == 0) ? -1 : __ldg(&gid[i - 1]);
        for (int g = gp + 1; g <= gi; g++) g_gstart[g] = i;
        if (i == N_NODES - 1)
            for (int g = gi + 1; g <= N_GRAPHS; g++) g_gstart[g] = N_NODES;
    }
    grid_bar(gridDim.x);

    // ---- P1: degrees ----
    for (int e = t; e < N_EDGES; e += NT) {
        atomicAdd(&g_deg_out[src[e]], 1);
        atomicAdd(&g_deg_in[dst[e]], 1);
    }
    grid_bar(gridDim.x);

    // ---- P2: exclusive scan of deg_in (blocks < SCAN_NB), coeffs ----
    if (blockIdx.x < SCAN_NB) {
        int b = blockIdx.x;
        int i = b * SCAN_BS + threadIdx.x;
        int lane = threadIdx.x & 31, wid = threadIdx.x >> 5;
        int v = (i < N_NODES) ? g_deg_in[i] : 0;
        int x = v;
#pragma unroll
        for (int o = 1; o < 32; o <<= 1) {
            int y = __shfl_up_sync(0xFFFFFFFFu, x, o);
            if (lane >= o) x += y;
        }
        __shared__ int wsum[32];
        __shared__ int s_prefix;
        if (lane == 31) wsum[wid] = x;
        __syncthreads();
        if (wid == 0) {
            int w = wsum[lane];
#pragma unroll
            for (int o = 1; o < 32; o <<= 1) {
                int y = __shfl_up_sync(0xFFFFFFFFu, w, o);
                if (lane >= o) w += y;
            }
            wsum[lane] = w;
        }
        __syncthreads();
        int excl = x - v + (wid > 0 ? wsum[wid - 1] : 0);

        if (threadIdx.x == 0) {
            g_scanagg[b] = wsum[31];
            __threadfence();
            atomicExch(&g_scanflag[b], 1);
        }
        if (wid == 0) {
            int pre = 0;
            for (int base = 0; base < b; base += 32) {
                int idx = base + lane;
                int val = 0;
                if (idx < b) {
                    while (atomicAdd(&g_scanflag[idx], 0) == 0) {}
                    val = g_scanagg[idx];
                }
#pragma unroll
                for (int o = 16; o > 0; o >>= 1)
                    val += __shfl_xor_sync(0xFFFFFFFFu, val, o);
                pre += val;
            }
            if (lane == 0) s_prefix = pre;
        }
        __syncthreads();
        int prefix = s_prefix;

        if (i < N_NODES) {
            int r = excl + prefix;
            g_rowstart[i] = r;
            g_fill[i] = r;
            g_cout[i] = rsqrtf(fmaxf((float)g_deg_out[i], 1.0f));
            g_cin[i]  = rsqrtf(fmaxf((float)g_deg_in[i], 1.0f));
        }
        if (i == 0) g_rowstart[N_NODES] = N_EDGES;
    }
    grid_bar(gridDim.x);

    // ---- P3: CSR fill + feats -> bf16 pre-scaled by c_out ----
    for (int e = t; e < N_EDGES; e += NT) {
        int pos = atomicAdd(&g_fill[dst[e]], 1);
        g_csr_src[pos] = src[e];
    }
    constexpr int CPN = IN_FEATS / 4;   // float4 chunks per node (16)
    for (int idx = t; idx < N_NODES * CPN; idx += NT) {
        int node = idx / CPN;
        int l4 = idx % CPN;
        float co = g_cout[node];
        float4 fv = __ldg(reinterpret_cast<const float4*>(
            feats + (size_t)node * IN_FEATS + l4 * 4));
        uint2 st;
        st.x = f2bf2(fv.x * co, fv.y * co);
        st.y = f2bf2(fv.z * co, fv.w * co);
        *reinterpret_cast<uint2*>(g_f16 + (size_t)node * IN_FEATS + l4 * 4) = st;
    }
}

// ---------------- bf16 pull aggregation (4-edge unrolled) --------------------
// agg16[d] = c_in[d] * sum_{s in N(d)} x16[s]   (x16 already carries c_out)
template <int F>
__global__ __launch_bounds__(256)
void pull_bf16_kernel(const __nv_bfloat16* __restrict__ x16) {
    constexpr int LPN = F / 8;                 // lanes per node
    int t = blockIdx.x * blockDim.x + threadIdx.x;
    int node = t / LPN;
    int lane = t % LPN;
    if (node >= N_NODES) return;
    int j = g_rowstart[node];
    int end = g_rowstart[node + 1];
    u64 A0 = 0ull, A1 = 0ull, A2 = 0ull, A3 = 0ull;   // packed f32x2 accumulators
    // 4-edge unroll: 4 independent index loads then 4 independent gathers
    for (; j + 3 < end; j += 4) {
        int s0 = __ldg(&g_csr_src[j]);
        int s1 = __ldg(&g_csr_src[j + 1]);
        int s2 = __ldg(&g_csr_src[j + 2]);
        int s3 = __ldg(&g_csr_src[j + 3]);
        uint4 u0 = __ldg(reinterpret_cast<const uint4*>(x16 + (size_t)s0 * F + lane * 8));
        uint4 u1 = __ldg(reinterpret_cast<const uint4*>(x16 + (size_t)s1 * F + lane * 8));
        uint4 u2 = __ldg(reinterpret_cast<const uint4*>(x16 + (size_t)s2 * F + lane * 8));
        uint4 u3 = __ldg(reinterpret_cast<const uint4*>(x16 + (size_t)s3 * F + lane * 8));
        acc_f32x2(A0, hadd2u(u0.x, u1.x));
        acc_f32x2(A1, hadd2u(u0.y, u1.y));
        acc_f32x2(A2, hadd2u(u0.z, u1.z));
        acc_f32x2(A3, hadd2u(u0.w, u1.w));
        acc_f32x2(A0, hadd2u(u2.x, u3.x));
        acc_f32x2(A1, hadd2u(u2.y, u3.y));
        acc_f32x2(A2, hadd2u(u2.z, u3.z));
        acc_f32x2(A3, hadd2u(u2.w, u3.w));
    }
    if (j + 1 < end) {
        int s0 = __ldg(&g_csr_src[j]);
        int s1 = __ldg(&g_csr_src[j + 1]);
        uint4 u0 = __ldg(reinterpret_cast<const uint4*>(x16 + (size_t)s0 * F + lane * 8));
        uint4 u1 = __ldg(reinterpret_cast<const uint4*>(x16 + (size_t)s1 * F + lane * 8));
        acc_f32x2(A0, hadd2u(u0.x, u1.x));
        acc_f32x2(A1, hadd2u(u0.y, u1.y));
        acc_f32x2(A2, hadd2u(u0.z, u1.z));
        acc_f32x2(A3, hadd2u(u0.w, u1.w));
        j += 2;
    }
    if (j < end) {
        int s0 = __ldg(&g_csr_src[j]);
        uint4 u0 = __ldg(reinterpret_cast<const uint4*>(x16 + (size_t)s0 * F + lane * 8));
        acc_f32x2(A0, u0.x);
        acc_f32x2(A1, u0.y);
        acc_f32x2(A2, u0.z);
        acc_f32x2(A3, u0.w);
    }
    float ci = __ldg(&g_cin[node]);
    float2 f0 = unpack_f32x2(A0);
    float2 f1 = unpack_f32x2(A1);
    float2 f2 = unpack_f32x2(A2);
    float2 f3 = unpack_f32x2(A3);
    uint4 o;
    o.x = f2bf2(f0.x * ci, f0.y * ci);
    o.y = f2bf2(f1.x * ci, f1.y * ci);
    o.z = f2bf2(f2.x * ci, f2.y * ci);
    o.w = f2bf2(f3.x * ci, f3.y * ci);
    *reinterpret_cast<uint4*>(g_agg16 + (size_t)node * F + lane * 8) = o;
}

// ---------------- tensor-core GEMM (bf16 m16n8k16 mma.sync): -----------------
// F32OUT: write fp32 to C32 (for the pooled layer). Else bf16 to C16.
template <int FIN, bool RELU, bool SCALE_OUT, bool F32OUT>
__global__ __launch_bounds__(256)
void gemm_tc_kernel(const __nv_bfloat16* __restrict__ A16,
                    const float* __restrict__ W,
                    const float* __restrict__ bias,
                    __nv_bfloat16* __restrict__ C16,
                    float* __restrict__ C32) {
    extern __shared__ uint32_t smem[];
    constexpr int KPAD = FIN + 8;          // u16 units per A row
    constexpr int NPAD = 136;              // u32 units per W kpair row
    constexpr int NCH = FIN / 32;          // 32-k chunks
    uint16_t* At = reinterpret_cast<uint16_t*>(smem);        // 64 * KPAD u16
    uint32_t* Ws = smem + (64 * KPAD) / 2;                    // 2 * 16 * NPAD u32

    int tid = threadIdx.x;
    int warp = tid >> 5;
    int lane = tid & 31;
    int rowBase = blockIdx.x * 64;

    constexpr int C8 = FIN / 8;            // uint4 chunks per row
    for (int t = tid; t < 64 * C8; t += 256) {
        int row = t / C8;
        int k8 = t % C8;
        int gr = rowBase + row;
        uint4 u = make_uint4(0u, 0u, 0u, 0u);
        if (gr < N_NODES)
            u = __ldg(reinterpret_cast<const uint4*>(A16 + (size_t)gr * FIN + k8 * 8));
        *reinterpret_cast<uint4*>(At + row * KPAD + k8 * 8) = u;
    }
    {
#pragma unroll
        for (int t = 0; t < 4; t++) {
            int p = tid + t * 256;
            int kp = p >> 6;
            int n = (p & 63) * 2;
            float2 lo = __ldg(reinterpret_cast<const float2*>(W + (size_t)(2 * kp) * 128 + n));
            float2 hi = __ldg(reinterpret_cast<const float2*>(W + (size_t)(2 * kp + 1) * 128 + n));
            uint2 st;
            st.x = f2bf2(lo.x, hi.x);
            st.y = f2bf2(lo.y, hi.y);
            *reinterpret_cast<uint2*>(Ws + kp * NPAD + n) = st;
        }
    }
    __syncthreads();

    int m0 = (warp & 3) * 16;
    int n0 = (warp >> 2) * 64;
    int lq = lane & 3;
    int lg = lane >> 2;

    float acc[8][4];
#pragma unroll
    for (int nt = 0; nt < 8; nt++)
#pragma unroll
        for (int j = 0; j < 4; j++) acc[nt][j] = 0.f;

    const uint16_t* arow0 = At + (m0 + lg) * KPAD + 2 * lq;
    const uint16_t* arow1 = arow0 + 8 * KPAD;

#pragma unroll
    for (int ch = 0; ch < NCH; ch++) {
        int cur = ch & 1;
        if (ch + 1 < NCH) {
#pragma unroll
            for (int t = 0; t < 4; t++) {
                int p = tid + t * 256;
                int kp = p >> 6;
                int n = (p & 63) * 2;
                int kg = (ch + 1) * 32 + 2 * kp;
                float2 lo = __ldg(reinterpret_cast<const float2*>(W + (size_t)kg * 128 + n));
                float2 hi = __ldg(reinterpret_cast<const float2*>(W + (size_t)(kg + 1) * 128 + n));
                uint2 st;
                st.x = f2bf2(lo.x, hi.x);
                st.y = f2bf2(lo.y, hi.y);
                *reinterpret_cast<uint2*>(Ws + (cur ^ 1) * 16 * NPAD + kp * NPAD + n) = st;
            }
        }
        const uint32_t* wsb = Ws + cur * 16 * NPAD;
#pragma unroll
        for (int ks = 0; ks < 2; ks++) {
            int kb = ch * 32 + ks * 16;
            uint32_t a0 = *reinterpret_cast<const uint32_t*>(arow0 + kb);
            uint32_t a1 = *reinterpret_cast<const uint32_t*>(arow1 + kb);
            uint32_t a2 = *reinterpret_cast<const uint32_t*>(arow0 + kb + 8);
            uint32_t a3 = *reinterpret_cast<const uint32_t*>(arow1 + kb + 8);
            const uint32_t* b0row = wsb + (ks * 8 + lq) * NPAD + n0 + lg;
            const uint32_t* b1row = b0row + 4 * NPAD;
#pragma unroll
            for (int nt = 0; nt < 8; nt++) {
                uint32_t b0 = b0row[nt * 8];
                uint32_t b1 = b1row[nt * 8];
                mma_bf16(acc[nt][0], acc[nt][1], acc[nt][2], acc[nt][3],
                         a0, a1, a2, a3, b0, b1);
            }
        }
        if (ch + 1 < NCH) __syncthreads();
    }

    int r_lo = rowBase + m0 + lg;
    int r_hi = r_lo + 8;
    float co_lo = 1.f, co_hi = 1.f;
    if (SCALE_OUT) {
        if (r_lo < N_NODES) co_lo = __ldg(&g_cout[r_lo]);
        if (r_hi < N_NODES) co_hi = __ldg(&g_cout[r_hi]);
    }
#pragma unroll
    for (int nt = 0; nt < 8; nt++) {
        int col = n0 + nt * 8 + 2 * lq;
        float2 bb = __ldg(reinterpret_cast<const float2*>(bias + col));
        float v0 = acc[nt][0] + bb.x, v1 = acc[nt][1] + bb.y;
        float v2 = acc[nt][2] + bb.x, v3 = acc[nt][3] + bb.y;
        if (RELU) {
            v0 = fmaxf(v0, 0.f); v1 = fmaxf(v1, 0.f);
            v2 = fmaxf(v2, 0.f); v3 = fmaxf(v3, 0.f);
        }
        if (SCALE_OUT) { v0 *= co_lo; v1 *= co_lo; v2 *= co_hi; v3 *= co_hi; }
        if (r_lo < N_NODES) {
            if (F32OUT) {
                *reinterpret_cast<float2*>(C32 + (size_t)r_lo * 128 + col) = make_float2(v0, v1);
            } else {
                *reinterpret_cast<uint32_t*>(C16 + (size_t)r_lo * 128 + col) = f2bf2(v0, v1);
            }
        }
        if (r_hi < N_NODES) {
            if (F32OUT) {
                *reinterpret_cast<float2*>(C32 + (size_t)r_hi * 128 + col) = make_float2(v2, v3);
            } else {
                *reinterpret_cast<uint32_t*>(C16 + (size_t)r_hi * 128 + col) = f2bf2(v2, v3);
            }
        }
    }
}

// ---------------- segmented mean-pool: one block per graph (no atomics) ------
__global__ __launch_bounds__(128)
void pool_kernel() {
    int g = blockIdx.x;
    int c = threadIdx.x;          // column 0..127
    int s = g_gstart[g];
    int e = g_gstart[g + 1];
    float sum = 0.f;
    for (int i = s; i < e; i++)
        sum += g_y3f[(size_t)i * 128 + c];
    float cnt = (float)(e - s);
    g_gsum[(size_t)g * 128 + c] = sum / fmaxf(cnt, 1.0f);
}

// ---------------- fused MLP head (16 graphs per block) -----------------------
__global__ __launch_bounds__(256)
void mlp_kernel(const float* __restrict__ fg,
                const float* __restrict__ Wl1, const float* __restrict__ bl1,
                const float* __restrict__ Wl2, const float* __restrict__ bl2,
                const float* __restrict__ Wl3, const float* __restrict__ bl3,
                float* __restrict__ out) {
    __shared__ float in_s[16][132];
    __shared__ float h_s[16][256];

    int tid = threadIdx.x;
    int gBase = blockIdx.x * 16;

    for (int idx = tid; idx < 16 * 128; idx += 256) {
        int gl = idx >> 7, f = idx & 127;
        int g = gBase + gl;
        in_s[gl][f] = g_gsum[(size_t)g * 128 + f];   // already the mean
    }
    for (int idx = tid; idx < 16 * 3; idx += 256) {
        int gl = idx / 3, f = idx % 3;
        in_s[gl][128 + f] = fg[(size_t)(gBase + gl) * 3 + f];
    }
    __syncthreads();

    float acc[16];
    {
        float b = bl1[tid];
#pragma unroll
        for (int g = 0; g < 16; g++) acc[g] = b;
        for (int i = 0; i < 131; i++) {
            float w = __ldg(&Wl1[(size_t)i * 256 + tid]);
#pragma unroll
            for (int g = 0; g < 16; g++) acc[g] = fmaf(in_s[g][i], w, acc[g]);
        }
#pragma unroll
        for (int g = 0; g < 16; g++) h_s[g][tid] = fmaxf(acc[g], 0.f);
    }
    __syncthreads();
    {
        float b = bl2[tid];
#pragma unroll
        for (int g = 0; g < 16; g++) acc[g] = b;
        for (int i = 0; i < 256; i++) {
            float w = __ldg(&Wl2[(size_t)i * 256 + tid]);
#pragma unroll
            for (int g = 0; g < 16; g++) acc[g] = fmaf(h_s[g][i], w, acc[g]);
        }
        __syncthreads();
#pragma unroll
        for (int g = 0; g < 16; g++) h_s[g][tid] = fmaxf(acc[g], 0.f);
    }
    __syncthreads();
    {
        int g = tid >> 4;
        int lane = tid & 15;
        float s = 0.f;
        for (int j = lane; j < 256; j += 16) s += h_s[g][j] * __ldg(&Wl3[j]);
#pragma unroll
        for (int off = 8; off > 0; off >>= 1)
            s += __shfl_down_sync(0xFFFFFFFFu, s, off, 16);
        if (lane == 0) out[gBase + g] = s + bl3[0];
    }
}

// ---------------- launch -----------------------------------------------------
extern "C" void kernel_launch(void* const* d_in, const int* in_sizes, int n_in,
                              void* d_out, int out_size) {
    const float* feats_node  = (const float*)d_in[0];
    const float* feats_graph = (const float*)d_in[1];
    const float* W1 = (const float*)d_in[2];
    const float* b1 = (const float*)d_in[3];
    const float* W2 = (const float*)d_in[4];
    const float* b2 = (const float*)d_in[5];
    const float* W3 = (const float*)d_in[6];
    const float* b3 = (const float*)d_in[7];
    const float* Wl1 = (const float*)d_in[8];
    const float* bl1 = (const float*)d_in[9];
    const float* Wl2 = (const float*)d_in[10];
    const float* bl2 = (const float*)d_in[11];
    const float* Wl3 = (const float*)d_in[12];
    const float* bl3 = (const float*)d_in[13];
    const int* src = (const int*)d_in[14];
    const int* dst = (const int*)d_in[15];
    const int* gid = (const int*)d_in[16];
    float* out = (float*)d_out;

    void *p_agg16, *p_f16, *p_x16, *p_y16, *p_y3f;
    cudaGetSymbolAddress(&p_agg16, g_agg16);
    cudaGetSymbolAddress(&p_f16, g_f16);
    cudaGetSymbolAddress(&p_x16, g_x16);
    cudaGetSymbolAddress(&p_y16, g_y16);
    cudaGetSymbolAddress(&p_y3f, g_y3f);
    __nv_bfloat16* agg16 = (__nv_bfloat16*)p_agg16;
    __nv_bfloat16* f16 = (__nv_bfloat16*)p_f16;
    __nv_bfloat16* x16 = (__nv_bfloat16*)p_x16;
    __nv_bfloat16* y16 = (__nv_bfloat16*)p_y16;
    float* y3f = (float*)p_y3f;

    const int SMEM64  = 64 * (IN_FEATS + 8) * 2 + 2 * 16 * 136 * 4;   // 26624
    const int SMEM128 = 64 * (HIDDEN + 8) * 2   + 2 * 16 * 136 * 4;   // 34816

    // --- fused preprocessing (zero, gstart, degree, scan/coeff, fill, feats->bf16)
    prepass_kernel<<<PRE_NB, SCAN_BS>>>(src, dst, gid, feats_node);

    const int gemm_blocks = (N_NODES + 63) / 64;

    // ---- layer 1 ----
    pull_bf16_kernel<IN_FEATS><<<(N_NODES * (IN_FEATS / 8) + 255) / 256, 256>>>(f16);
    gemm_tc_kernel<IN_FEATS, true, true, false><<<gemm_blocks, 256, SMEM64>>>(agg16, W1, b1, x16, nullptr);

    // ---- layer 2 ----
    pull_bf16_kernel<HIDDEN><<<(N_NODES * (HIDDEN / 8) + 255) / 256, 256>>>(x16);
    gemm_tc_kernel<HIDDEN, true, true, false><<<gemm_blocks, 256, SMEM128>>>(agg16, W2, b2, y16, nullptr);

    // ---- layer 3: fp32 output, then segmented mean-pool (no atomics) ----
    pull_bf16_kernel<HIDDEN><<<(N_NODES * (HIDDEN / 8) + 255) / 256, 256>>>(y16);
    gemm_tc_kernel<HIDDEN, false, false, true><<<gemm_blocks, 256, SMEM128>>>(agg16, W3, b3, nullptr, y3f);
    pool_kernel<<<N_GRAPHS, 128>>>();

    // ---- MLP head ----
    mlp_kernel<<<N_GRAPHS / 16, 256>>>(feats_graph, Wl1, bl1, Wl2, bl2, Wl3, bl3, out);
}

// round 13
// speedup vs baseline: 1.2702x; 1.2702x over previous
#include <cuda_runtime.h>
#include <cuda_bf16.h>
#include <cstdint>

#define N_NODES 50000
#define N_EDGES 600000
#define N_GRAPHS 2000
#define IN_FEATS 64
#define HIDDEN 128
#define SCAN_BS 1024
#define SCAN_NB ((N_NODES + SCAN_BS - 1) / SCAN_BS)   // 49
#define PRE_NB 98

typedef unsigned long long u64;

// ---------------- scratch (device globals; no allocation allowed) ----------
__device__ int   g_deg_out[N_NODES];
__device__ int   g_deg_in[N_NODES];
__device__ float g_cout[N_NODES];
__device__ float g_cin[N_NODES];
__device__ int   g_rowstart[N_NODES + 1];
__device__ int   g_fill[N_NODES];
__device__ int   g_scanagg[SCAN_NB];
__device__ int   g_scanflag[SCAN_NB];
__device__ int   g_csr_src[N_EDGES];
__device__ int   g_bar_cnt;
__device__ int   g_bar_gen;
__device__ __nv_bfloat16 g_agg16[(size_t)N_NODES * HIDDEN];  // pull output (bf16)
__device__ __nv_bfloat16 g_f16[(size_t)N_NODES * IN_FEATS];  // feats * c_out
__device__ __nv_bfloat16 g_x16[(size_t)N_NODES * HIDDEN];    // layer1 out * c_out
__device__ __nv_bfloat16 g_y16[(size_t)N_NODES * HIDDEN];    // layer2 out * c_out
__device__ float g_gsum[(size_t)N_GRAPHS * HIDDEN];
__device__ int   g_gcnt[N_GRAPHS];

// ---------------- helpers ---------------------------------------------------
__device__ __forceinline__ void red_add_v2(float* p, float x, float y) {
    asm volatile("red.global.add.v2.f32 [%0], {%1, %2};"
                 :: "l"(p), "f"(x), "f"(y) : "memory");
}
__device__ __forceinline__ void mma_bf16(float& d0, float& d1, float& d2, float& d3,
                                         uint32_t a0, uint32_t a1, uint32_t a2, uint32_t a3,
                                         uint32_t b0, uint32_t b1) {
    asm volatile(
        "mma.sync.aligned.m16n8k16.row.col.f32.bf16.bf16.f32 "
        "{%0,%1,%2,%3}, {%4,%5,%6,%7}, {%8,%9}, {%0,%1,%2,%3};"
        : "+f"(d0), "+f"(d1), "+f"(d2), "+f"(d3)
        : "r"(a0), "r"(a1), "r"(a2), "r"(a3), "r"(b0), "r"(b1));
}
__device__ __forceinline__ uint32_t f2bf2(float lo, float hi) {
    __nv_bfloat162 h = __floats2bfloat162_rn(lo, hi);
    return *reinterpret_cast<uint32_t*>(&h);
}
// packed bf16x2 add (HADD2.BF16_V2) on raw u32 carriers
__device__ __forceinline__ uint32_t hadd2u(uint32_t a, uint32_t b) {
    __nv_bfloat162 ha = *reinterpret_cast<__nv_bfloat162*>(&a);
    __nv_bfloat162 hb = *reinterpret_cast<__nv_bfloat162*>(&b);
    __nv_bfloat162 r = __hadd2(ha, hb);
    return *reinterpret_cast<uint32_t*>(&r);
}
// accumulate a bf16x2 pair into a packed f32x2 accumulator (exact expand)
__device__ __forceinline__ void acc_f32x2(u64& acc, uint32_t p) {
    asm("{\n\t"
        ".reg .b32 lo, hi;\n\t"
        ".reg .b64 v;\n\t"
        "shl.b32 lo, %1, 16;\n\t"
        "and.b32 hi, %1, 0xFFFF0000;\n\t"
        "mov.b64 v, {lo, hi};\n\t"
        "add.rn.f32x2 %0, %0, v;\n\t"
        "}" : "+l"(acc) : "r"(p));
}
__device__ __forceinline__ float2 unpack_f32x2(u64 v) {
    float2 f; asm("mov.b64 {%0, %1}, %2;" : "=f"(f.x), "=f"(f.y) : "l"(v)); return f;
}

// software grid barrier (all 98 blocks co-resident on 148 SMs)
__device__ __forceinline__ void grid_bar(int nb) {
    __syncthreads();
    if (threadIdx.x == 0) {
        int gen = atomicAdd(&g_bar_gen, 0);
        __threadfence();
        int arrived = atomicAdd(&g_bar_cnt, 1) + 1;
        if (arrived == nb) {
            g_bar_cnt = 0;
            __threadfence();
            atomicAdd(&g_bar_gen, 1);
        } else {
            while (atomicAdd(&g_bar_gen, 0) == gen) {}
        }
        __threadfence();
    }
    __syncthreads();
}

// ---------------- fused prepass: zero -> degree -> scan/coeff -> fill+feats ---
__global__ __launch_bounds__(SCAN_BS)
void prepass_kernel(const int* __restrict__ src, const int* __restrict__ dst,
                    const int* __restrict__ gid, const float* __restrict__ feats) {
    const int NT = gridDim.x * blockDim.x;
    const int t = blockIdx.x * blockDim.x + threadIdx.x;

    // ---- P0: zero everything consumed later ----
    for (int i = t; i < N_NODES; i += NT) { g_deg_out[i] = 0; g_deg_in[i] = 0; }
    for (int i = t; i < N_GRAPHS; i += NT) g_gcnt[i] = 0;
    for (int i = t; i < SCAN_NB; i += NT) g_scanflag[i] = 0;
    for (int i = t; i < N_GRAPHS * HIDDEN; i += NT) g_gsum[i] = 0.0f;
    grid_bar(gridDim.x);

    // ---- P1: degrees ----
    for (int e = t; e < N_EDGES; e += NT) {
        atomicAdd(&g_deg_out[src[e]], 1);
        atomicAdd(&g_deg_in[dst[e]], 1);
    }
    grid_bar(gridDim.x);

    // ---- P2: exclusive scan of deg_in (blocks < SCAN_NB), coeffs, gcnt ----
    if (blockIdx.x < SCAN_NB) {
        int b = blockIdx.x;
        int i = b * SCAN_BS + threadIdx.x;
        int lane = threadIdx.x & 31, wid = threadIdx.x >> 5;
        int v = (i < N_NODES) ? g_deg_in[i] : 0;
        int x = v;
#pragma unroll
        for (int o = 1; o < 32; o <<= 1) {
            int y = __shfl_up_sync(0xFFFFFFFFu, x, o);
            if (lane >= o) x += y;
        }
        __shared__ int wsum[32];
        __shared__ int s_prefix;
        if (lane == 31) wsum[wid] = x;
        __syncthreads();
        if (wid == 0) {
            int w = wsum[lane];
#pragma unroll
            for (int o = 1; o < 32; o <<= 1) {
                int y = __shfl_up_sync(0xFFFFFFFFu, w, o);
                if (lane >= o) w += y;
            }
            wsum[lane] = w;
        }
        __syncthreads();
        int excl = x - v + (wid > 0 ? wsum[wid - 1] : 0);

        if (threadIdx.x == 0) {
            g_scanagg[b] = wsum[31];
            __threadfence();
            atomicExch(&g_scanflag[b], 1);
        }
        if (wid == 0) {
            int pre = 0;
            for (int base = 0; base < b; base += 32) {
                int idx = base + lane;
                int val = 0;
                if (idx < b) {
                    while (atomicAdd(&g_scanflag[idx], 0) == 0) {}
                    val = g_scanagg[idx];
                }
#pragma unroll
                for (int o = 16; o > 0; o >>= 1)
                    val += __shfl_xor_sync(0xFFFFFFFFu, val, o);
                pre += val;
            }
            if (lane == 0) s_prefix = pre;
        }
        __syncthreads();
        int prefix = s_prefix;

        if (i < N_NODES) {
            int r = excl + prefix;
            g_rowstart[i] = r;
            g_fill[i] = r;
            g_cout[i] = rsqrtf(fmaxf((float)g_deg_out[i], 1.0f));
            g_cin[i]  = rsqrtf(fmaxf((float)g_deg_in[i], 1.0f));
            atomicAdd(&g_gcnt[gid[i]], 1);
        }
        if (i == 0) g_rowstart[N_NODES] = N_EDGES;
    }
    grid_bar(gridDim.x);

    // ---- P3: CSR fill + feats -> bf16 pre-scaled by c_out ----
    for (int e = t; e < N_EDGES; e += NT) {
        int pos = atomicAdd(&g_fill[dst[e]], 1);
        g_csr_src[pos] = src[e];
    }
    constexpr int CPN = IN_FEATS / 4;   // float4 chunks per node (16)
    for (int idx = t; idx < N_NODES * CPN; idx += NT) {
        int node = idx / CPN;
        int l4 = idx % CPN;
        float co = g_cout[node];
        float4 fv = __ldg(reinterpret_cast<const float4*>(
            feats + (size_t)node * IN_FEATS + l4 * 4));
        uint2 st;
        st.x = f2bf2(fv.x * co, fv.y * co);
        st.y = f2bf2(fv.z * co, fv.w * co);
        *reinterpret_cast<uint2*>(g_f16 + (size_t)node * IN_FEATS + l4 * 4) = st;
    }
}

// ---------------- bf16 pull aggregation (software-pipelined indices) ---------
// agg16[d] = c_in[d] * sum_{s in N(d)} x16[s]   (x16 already carries c_out)
// Indices for iteration p+1 load during iteration p's gathers.
template <int F>
__global__ __launch_bounds__(256)
void pull_bf16_kernel(const __nv_bfloat16* __restrict__ x16) {
    constexpr int LPN = F / 8;                 // lanes per node
    int t = blockIdx.x * blockDim.x + threadIdx.x;
    int node = t / LPN;
    int lane = t % LPN;
    if (node >= N_NODES) return;
    int j = g_rowstart[node];
    int end = g_rowstart[node + 1];
    int pairs = (end - j) >> 1;
    u64 A0 = 0ull, A1 = 0ull, A2 = 0ull, A3 = 0ull;   // packed f32x2 accumulators

    int s0 = 0, s1 = 0;
    if (pairs > 0) {
        s0 = __ldg(&g_csr_src[j]);
        s1 = __ldg(&g_csr_src[j + 1]);
    }
    for (int p = 0; p < pairs; p++) {
        // gathers issue immediately from already-available indices
        uint4 u0 = __ldg(reinterpret_cast<const uint4*>(x16 + (size_t)s0 * F + lane * 8));
        uint4 u1 = __ldg(reinterpret_cast<const uint4*>(x16 + (size_t)s1 * F + lane * 8));
        // prefetch next pair of indices in the gather shadow
        if (p + 1 < pairs) {
            s0 = __ldg(&g_csr_src[j + 2 * p + 2]);
            s1 = __ldg(&g_csr_src[j + 2 * p + 3]);
        }
        acc_f32x2(A0, hadd2u(u0.x, u1.x));
        acc_f32x2(A1, hadd2u(u0.y, u1.y));
        acc_f32x2(A2, hadd2u(u0.z, u1.z));
        acc_f32x2(A3, hadd2u(u0.w, u1.w));
    }
    if ((end - j) & 1) {
        int sl = __ldg(&g_csr_src[end - 1]);
        uint4 u0 = __ldg(reinterpret_cast<const uint4*>(x16 + (size_t)sl * F + lane * 8));
        acc_f32x2(A0, u0.x);
        acc_f32x2(A1, u0.y);
        acc_f32x2(A2, u0.z);
        acc_f32x2(A3, u0.w);
    }
    float ci = __ldg(&g_cin[node]);
    float2 f0 = unpack_f32x2(A0);
    float2 f1 = unpack_f32x2(A1);
    float2 f2 = unpack_f32x2(A2);
    float2 f3 = unpack_f32x2(A3);
    uint4 o;
    o.x = f2bf2(f0.x * ci, f0.y * ci);
    o.y = f2bf2(f1.x * ci, f1.y * ci);
    o.z = f2bf2(f2.x * ci, f2.y * ci);
    o.w = f2bf2(f3.x * ci, f3.y * ci);
    *reinterpret_cast<uint4*>(g_agg16 + (size_t)node * F + lane * 8) = o;
}

// ---------------- tensor-core GEMM (bf16 m16n8k16 mma.sync): -----------------
template <int FIN, bool RELU, bool SCALE_OUT, bool POOL>
__global__ __launch_bounds__(256)
void gemm_tc_kernel(const __nv_bfloat16* __restrict__ A16,
                    const float* __restrict__ W,
                    const float* __restrict__ bias,
                    __nv_bfloat16* __restrict__ C16,
                    const int* __restrict__ gid) {
    extern __shared__ uint32_t smem[];
    constexpr int KPAD = FIN + 8;          // u16 units per A row
    constexpr int NPAD = 136;              // u32 units per W kpair row
    constexpr int NCH = FIN / 32;          // 32-k chunks
    uint16_t* At = reinterpret_cast<uint16_t*>(smem);        // 64 * KPAD u16
    uint32_t* Ws = smem + (64 * KPAD) / 2;                    // 2 * 16 * NPAD u32

    int tid = threadIdx.x;
    int warp = tid >> 5;
    int lane = tid & 31;
    int rowBase = blockIdx.x * 64;

    constexpr int C8 = FIN / 8;            // uint4 chunks per row
    for (int t = tid; t < 64 * C8; t += 256) {
        int row = t / C8;
        int k8 = t % C8;
        int gr = rowBase + row;
        uint4 u = make_uint4(0u, 0u, 0u, 0u);
        if (gr < N_NODES)
            u = __ldg(reinterpret_cast<const uint4*>(A16 + (size_t)gr * FIN + k8 * 8));
        *reinterpret_cast<uint4*>(At + row * KPAD + k8 * 8) = u;
    }
    {
#pragma unroll
        for (int t = 0; t < 4; t++) {
            int p = tid + t * 256;
            int kp = p >> 6;
            int n = (p & 63) * 2;
            float2 lo = __ldg(reinterpret_cast<const float2*>(W + (size_t)(2 * kp) * 128 + n));
            float2 hi = __ldg(reinterpret_cast<const float2*>(W + (size_t)(2 * kp + 1) * 128 + n));
            uint2 st;
            st.x = f2bf2(lo.x, hi.x);
            st.y = f2bf2(lo.y, hi.y);
            *reinterpret_cast<uint2*>(Ws + kp * NPAD + n) = st;
        }
    }
    __syncthreads();

    int m0 = (warp & 3) * 16;
    int n0 = (warp >> 2) * 64;
    int lq = lane & 3;
    int lg = lane >> 2;

    float acc[8][4];
#pragma unroll
    for (int nt = 0; nt < 8; nt++)
#pragma unroll
        for (int j = 0; j < 4; j++) acc[nt][j] = 0.f;

    const uint16_t* arow0 = At + (m0 + lg) * KPAD + 2 * lq;
    const uint16_t* arow1 = arow0 + 8 * KPAD;

#pragma unroll
    for (int ch = 0; ch < NCH; ch++) {
        int cur = ch & 1;
        if (ch + 1 < NCH) {
#pragma unroll
            for (int t = 0; t < 4; t++) {
                int p = tid + t * 256;
                int kp = p >> 6;
                int n = (p & 63) * 2;
                int kg = (ch + 1) * 32 + 2 * kp;
                float2 lo = __ldg(reinterpret_cast<const float2*>(W + (size_t)kg * 128 + n));
                float2 hi = __ldg(reinterpret_cast<const float2*>(W + (size_t)(kg + 1) * 128 + n));
                uint2 st;
                st.x = f2bf2(lo.x, hi.x);
                st.y = f2bf2(lo.y, hi.y);
                *reinterpret_cast<uint2*>(Ws + (cur ^ 1) * 16 * NPAD + kp * NPAD + n) = st;
            }
        }
        const uint32_t* wsb = Ws + cur * 16 * NPAD;
#pragma unroll
        for (int ks = 0; ks < 2; ks++) {
            int kb = ch * 32 + ks * 16;
            uint32_t a0 = *reinterpret_cast<const uint32_t*>(arow0 + kb);
            uint32_t a1 = *reinterpret_cast<const uint32_t*>(arow1 + kb);
            uint32_t a2 = *reinterpret_cast<const uint32_t*>(arow0 + kb + 8);
            uint32_t a3 = *reinterpret_cast<const uint32_t*>(arow1 + kb + 8);
            const uint32_t* b0row = wsb + (ks * 8 + lq) * NPAD + n0 + lg;
            const uint32_t* b1row = b0row + 4 * NPAD;
#pragma unroll
            for (int nt = 0; nt < 8; nt++) {
                uint32_t b0 = b0row[nt * 8];
                uint32_t b1 = b1row[nt * 8];
                mma_bf16(acc[nt][0], acc[nt][1], acc[nt][2], acc[nt][3],
                         a0, a1, a2, a3, b0, b1);
            }
        }
        if (ch + 1 < NCH) __syncthreads();
    }

    int r_lo = rowBase + m0 + lg;
    int r_hi = r_lo + 8;
    float co_lo = 1.f, co_hi = 1.f;
    if (SCALE_OUT) {
        if (r_lo < N_NODES) co_lo = __ldg(&g_cout[r_lo]);
        if (r_hi < N_NODES) co_hi = __ldg(&g_cout[r_hi]);
    }
    int g_lo = 0, g_hi = 0;
    if (POOL) {
        if (r_lo < N_NODES) g_lo = __ldg(&gid[r_lo]);
        if (r_hi < N_NODES) g_hi = __ldg(&gid[r_hi]);
    }
#pragma unroll
    for (int nt = 0; nt < 8; nt++) {
        int col = n0 + nt * 8 + 2 * lq;
        float2 bb = __ldg(reinterpret_cast<const float2*>(bias + col));
        float v0 = acc[nt][0] + bb.x, v1 = acc[nt][1] + bb.y;
        float v2 = acc[nt][2] + bb.x, v3 = acc[nt][3] + bb.y;
        if (RELU) {
            v0 = fmaxf(v0, 0.f); v1 = fmaxf(v1, 0.f);
            v2 = fmaxf(v2, 0.f); v3 = fmaxf(v3, 0.f);
        }
        if (SCALE_OUT) { v0 *= co_lo; v1 *= co_lo; v2 *= co_hi; v3 *= co_hi; }
        if (r_lo < N_NODES) {
            if (POOL) {
                red_add_v2(g_gsum + (size_t)g_lo * 128 + col, v0, v1);
            } else {
                *reinterpret_cast<uint32_t*>(C16 + (size_t)r_lo * 128 + col) = f2bf2(v0, v1);
            }
        }
        if (r_hi < N_NODES) {
            if (POOL) {
                red_add_v2(g_gsum + (size_t)g_hi * 128 + col, v2, v3);
            } else {
                *reinterpret_cast<uint32_t*>(C16 + (size_t)r_hi * 128 + col) = f2bf2(v2, v3);
            }
        }
    }
}

// ---------------- fused MLP head (16 graphs per block) — known-good ----------
__global__ __launch_bounds__(256)
void mlp_kernel(const float* __restrict__ fg,
                const float* __restrict__ Wl1, const float* __restrict__ bl1,
                const float* __restrict__ Wl2, const float* __restrict__ bl2,
                const float* __restrict__ Wl3, const float* __restrict__ bl3,
                float* __restrict__ out) {
    __shared__ float in_s[16][132];
    __shared__ float h_s[16][256];

    int tid = threadIdx.x;
    int gBase = blockIdx.x * 16;

    for (int idx = tid; idx < 16 * 128; idx += 256) {
        int gl = idx >> 7, f = idx & 127;
        int g = gBase + gl;
        float c = (float)g_gcnt[g];
        in_s[gl][f] = g_gsum[(size_t)g * 128 + f] / fmaxf(c, 1.0f);
    }
    for (int idx = tid; idx < 16 * 3; idx += 256) {
        int gl = idx / 3, f = idx % 3;
        in_s[gl][128 + f] = fg[(size_t)(gBase + gl) * 3 + f];
    }
    __syncthreads();

    float acc[16];
    {
        float b = bl1[tid];
#pragma unroll
        for (int g = 0; g < 16; g++) acc[g] = b;
        for (int i = 0; i < 131; i++) {
            float w = __ldg(&Wl1[(size_t)i * 256 + tid]);
#pragma unroll
            for (int g = 0; g < 16; g++) acc[g] = fmaf(in_s[g][i], w, acc[g]);
        }
#pragma unroll
        for (int g = 0; g < 16; g++) h_s[g][tid] = fmaxf(acc[g], 0.f);
    }
    __syncthreads();
    {
        float b = bl2[tid];
#pragma unroll
        for (int g = 0; g < 16; g++) acc[g] = b;
        for (int i = 0; i < 256; i++) {
            float w = __ldg(&Wl2[(size_t)i * 256 + tid]);
#pragma unroll
            for (int g = 0; g < 16; g++) acc[g] = fmaf(h_s[g][i], w, acc[g]);
        }
        __syncthreads();
#pragma unroll
        for (int g = 0; g < 16; g++) h_s[g][tid] = fmaxf(acc[g], 0.f);
    }
    __syncthreads();
    {
        int g = tid >> 4;
        int lane = tid & 15;
        float s = 0.f;
        for (int j = lane; j < 256; j += 16) s += h_s[g][j] * __ldg(&Wl3[j]);
#pragma unroll
        for (int off = 8; off > 0; off >>= 1)
            s += __shfl_down_sync(0xFFFFFFFFu, s, off, 16);
        if (lane == 0) out[gBase + g] = s + bl3[0];
    }
}

// ---------------- launch -----------------------------------------------------
extern "C" void kernel_launch(void* const* d_in, const int* in_sizes, int n_in,
                              void* d_out, int out_size) {
    const float* feats_node  = (const float*)d_in[0];
    const float* feats_graph = (const float*)d_in[1];
    const float* W1 = (const float*)d_in[2];
    const float* b1 = (const float*)d_in[3];
    const float* W2 = (const float*)d_in[4];
    const float* b2 = (const float*)d_in[5];
    const float* W3 = (const float*)d_in[6];
    const float* b3 = (const float*)d_in[7];
    const float* Wl1 = (const float*)d_in[8];
    const float* bl1 = (const float*)d_in[9];
    const float* Wl2 = (const float*)d_in[10];
    const float* bl2 = (const float*)d_in[11];
    const float* Wl3 = (const float*)d_in[12];
    const float* bl3 = (const float*)d_in[13];
    const int* src = (const int*)d_in[14];
    const int* dst = (const int*)d_in[15];
    const int* gid = (const int*)d_in[16];
    float* out = (float*)d_out;

    void *p_agg16, *p_f16, *p_x16, *p_y16;
    cudaGetSymbolAddress(&p_agg16, g_agg16);
    cudaGetSymbolAddress(&p_f16, g_f16);
    cudaGetSymbolAddress(&p_x16, g_x16);
    cudaGetSymbolAddress(&p_y16, g_y16);
    __nv_bfloat16* agg16 = (__nv_bfloat16*)p_agg16;
    __nv_bfloat16* f16 = (__nv_bfloat16*)p_f16;
    __nv_bfloat16* x16 = (__nv_bfloat16*)p_x16;
    __nv_bfloat16* y16 = (__nv_bfloat16*)p_y16;

    const int SMEM64  = 64 * (IN_FEATS + 8) * 2 + 2 * 16 * 136 * 4;   // 26624
    const int SMEM128 = 64 * (HIDDEN + 8) * 2   + 2 * 16 * 136 * 4;   // 34816

    // --- fused preprocessing (zero, degree, scan/coeff, fill, feats->bf16) ---
    prepass_kernel<<<PRE_NB, SCAN_BS>>>(src, dst, gid, feats_node);

    const int gemm_blocks = (N_NODES + 63) / 64;

    // ---- layer 1 ----
    pull_bf16_kernel<IN_FEATS><<<(N_NODES * (IN_FEATS / 8) + 255) / 256, 256>>>(f16);
    gemm_tc_kernel<IN_FEATS, true, true, false><<<gemm_blocks, 256, SMEM64>>>(agg16, W1, b1, x16, gid);

    // ---- layer 2 ----
    pull_bf16_kernel<HIDDEN><<<(N_NODES * (HIDDEN / 8) + 255) / 256, 256>>>(x16);
    gemm_tc_kernel<HIDDEN, true, true, false><<<gemm_blocks, 256, SMEM128>>>(agg16, W2, b2, y16, gid);

    // ---- layer 3 (+ fused mean-pool RED) ----
    pull_bf16_kernel<HIDDEN><<<(N_NODES * (HIDDEN / 8) + 255) / 256, 256>>>(y16);
    gemm_tc_kernel<HIDDEN, false, false, true><<<gemm_blocks, 256, SMEM128>>>(agg16, W3, b3, nullptr, gid);

    // ---- MLP head ----
    mlp_kernel<<<N_GRAPHS / 16, 256>>>(feats_graph, Wl1, bl1, Wl2, bl2, Wl3, bl3, out);
}

// round 14
// speedup vs baseline: 1.3032x; 1.0260x over previous
#include <cuda_runtime.h>
#include <cuda_bf16.h>
#include <cstdint>

#define N_NODES 50000
#define N_EDGES 600000
#define N_GRAPHS 2000
#define IN_FEATS 64
#define HIDDEN 128
#define SCAN_BS 1024
#define SCAN_NB ((N_NODES + SCAN_BS - 1) / SCAN_BS)   // 49
#define E_Q ((N_EDGES + 3) / 4)

typedef unsigned long long u64;

// ---------------- scratch (device globals; no allocation allowed) ----------
__device__ int   g_deg_out[N_NODES];
__device__ int   g_deg_in[N_NODES];
__device__ float g_cout[N_NODES];
__device__ float g_cin[N_NODES];
__device__ int   g_rowstart[N_NODES + 1];
__device__ int   g_fill[N_NODES];
__device__ int   g_scanagg[SCAN_NB];
__device__ int   g_scanflag[SCAN_NB];
__device__ int   g_csr_src[N_EDGES];
__device__ __nv_bfloat16 g_agg16[(size_t)N_NODES * HIDDEN];  // pull output (bf16)
__device__ __nv_bfloat16 g_f16[(size_t)N_NODES * IN_FEATS];  // feats * c_out
__device__ __nv_bfloat16 g_x16[(size_t)N_NODES * HIDDEN];    // layer1 out * c_out
__device__ __nv_bfloat16 g_y16[(size_t)N_NODES * HIDDEN];    // layer2 out * c_out
__device__ float g_gsum[(size_t)N_GRAPHS * HIDDEN];
__device__ int   g_gcnt[N_GRAPHS];

// ---------------- helpers ---------------------------------------------------
__device__ __forceinline__ void red_add_v2(float* p, float x, float y) {
    asm volatile("red.global.add.v2.f32 [%0], {%1, %2};"
                 :: "l"(p), "f"(x), "f"(y) : "memory");
}
__device__ __forceinline__ void mma_bf16(float& d0, float& d1, float& d2, float& d3,
                                         uint32_t a0, uint32_t a1, uint32_t a2, uint32_t a3,
                                         uint32_t b0, uint32_t b1) {
    asm volatile(
        "mma.sync.aligned.m16n8k16.row.col.f32.bf16.bf16.f32 "
        "{%0,%1,%2,%3}, {%4,%5,%6,%7}, {%8,%9}, {%0,%1,%2,%3};"
        : "+f"(d0), "+f"(d1), "+f"(d2), "+f"(d3)
        : "r"(a0), "r"(a1), "r"(a2), "r"(a3), "r"(b0), "r"(b1));
}
__device__ __forceinline__ uint32_t f2bf2(float lo, float hi) {
    __nv_bfloat162 h = __floats2bfloat162_rn(lo, hi);
    return *reinterpret_cast<uint32_t*>(&h);
}
// packed bf16x2 add (HADD2.BF16_V2) on raw u32 carriers
__device__ __forceinline__ uint32_t hadd2u(uint32_t a, uint32_t b) {
    __nv_bfloat162 ha = *reinterpret_cast<__nv_bfloat162*>(&a);
    __nv_bfloat162 hb = *reinterpret_cast<__nv_bfloat162*>(&b);
    __nv_bfloat162 r = __hadd2(ha, hb);
    return *reinterpret_cast<uint32_t*>(&r);
}
// accumulate a bf16x2 pair into a packed f32x2 accumulator (exact expand)
__device__ __forceinline__ void acc_f32x2(u64& acc, uint32_t p) {
    asm("{\n\t"
        ".reg .b32 lo, hi;\n\t"
        ".reg .b64 v;\n\t"
        "shl.b32 lo, %1, 16;\n\t"
        "and.b32 hi, %1, 0xFFFF0000;\n\t"
        "mov.b64 v, {lo, hi};\n\t"
        "add.rn.f32x2 %0, %0, v;\n\t"
        "}" : "+l"(acc) : "r"(p));
}
__device__ __forceinline__ float2 unpack_f32x2(u64 v) {
    float2 f; asm("mov.b64 {%0, %1}, %2;" : "=f"(f.x), "=f"(f.y) : "l"(v)); return f;
}

// ---------------- zero + degree -----------------------------------------------
__global__ void zero_misc_kernel() {
    int i = blockIdx.x * blockDim.x + threadIdx.x;
    if (i < N_NODES) { g_deg_out[i] = 0; g_deg_in[i] = 0; }
    if (i < N_GRAPHS) g_gcnt[i] = 0;
    if (i < SCAN_NB) g_scanflag[i] = 0;
}

__global__ void degree_kernel(const int* __restrict__ src, const int* __restrict__ dst) {
    int e = blockIdx.x * blockDim.x + threadIdx.x;
    if (e >= E_Q) return;
#pragma unroll
    for (int q = 0; q < 4; q++) {
        int idx = e + q * E_Q;
        if (idx < N_EDGES) {
            atomicAdd(&g_deg_out[src[idx]], 1);
            atomicAdd(&g_deg_in[dst[idx]], 1);
        }
    }
}

// ---------------- single-kernel scan (decoupled lookback) + finalize ---------
// Also converts feats_node -> bf16 pre-scaled by c_out, zeroes gsum.
__global__ __launch_bounds__(SCAN_BS)
void scan_kernel(const int* __restrict__ gid, const float* __restrict__ feats) {
    int b = blockIdx.x;
    int i = b * SCAN_BS + threadIdx.x;
    int lane = threadIdx.x & 31, wid = threadIdx.x >> 5;
    int v = (i < N_NODES) ? g_deg_in[i] : 0;
    int x = v;
#pragma unroll
    for (int o = 1; o < 32; o <<= 1) {
        int y = __shfl_up_sync(0xFFFFFFFFu, x, o);
        if (lane >= o) x += y;
    }
    __shared__ int wsum[32];
    __shared__ int s_prefix;
    if (lane == 31) wsum[wid] = x;
    __syncthreads();
    if (wid == 0) {
        int w = wsum[lane];
#pragma unroll
        for (int o = 1; o < 32; o <<= 1) {
            int y = __shfl_up_sync(0xFFFFFFFFu, w, o);
            if (lane >= o) w += y;
        }
        wsum[lane] = w;
    }
    __syncthreads();
    int excl = x - v + (wid > 0 ? wsum[wid - 1] : 0);

    if (threadIdx.x == 0) {
        g_scanagg[b] = wsum[31];
        __threadfence();
        atomicExch(&g_scanflag[b], 1);
    }
    if (wid == 0) {
        int pre = 0;
        for (int base = 0; base < b; base += 32) {
            int idx = base + lane;
            int val = 0;
            if (idx < b) {
                while (atomicAdd(&g_scanflag[idx], 0) == 0) {}
                val = g_scanagg[idx];
            }
#pragma unroll
            for (int o = 16; o > 0; o >>= 1)
                val += __shfl_xor_sync(0xFFFFFFFFu, val, o);
            pre += val;
        }
        if (lane == 0) s_prefix = pre;
    }
    __syncthreads();
    int prefix = s_prefix;

    if (i < N_NODES) {
        int r = excl + prefix;
        g_rowstart[i] = r;
        g_fill[i] = r;
        g_cout[i] = rsqrtf(fmaxf((float)g_deg_out[i], 1.0f));
        g_cin[i]  = rsqrtf(fmaxf((float)g_deg_in[i], 1.0f));
        atomicAdd(&g_gcnt[gid[i]], 1);
    }
    if (i == 0) g_rowstart[N_NODES] = N_EDGES;
    __syncthreads();   // g_cout for this block's node range now visible

    // convert this block's feats rows to bf16, pre-scaled by c_out (coalesced)
    constexpr int CPN = IN_FEATS / 4;   // float4 chunks per node (16)
    int nodeBase = b * SCAN_BS;
    for (int idx = threadIdx.x; idx < SCAN_BS * CPN; idx += SCAN_BS) {
        int node = nodeBase + idx / CPN;
        int l4 = idx % CPN;
        if (node < N_NODES) {
            float co = g_cout[node];
            float4 fv = __ldg(reinterpret_cast<const float4*>(
                feats + (size_t)node * IN_FEATS + l4 * 4));
            uint2 st;
            st.x = f2bf2(fv.x * co, fv.y * co);
            st.y = f2bf2(fv.z * co, fv.w * co);
            *reinterpret_cast<uint2*>(g_f16 + (size_t)node * IN_FEATS + l4 * 4) = st;
        }
    }

    for (int k = b * SCAN_BS + threadIdx.x; k < N_GRAPHS * HIDDEN; k += SCAN_NB * SCAN_BS)
        g_gsum[k] = 0.0f;
}

__global__ void fill_kernel(const int* __restrict__ src, const int* __restrict__ dst) {
    int e = blockIdx.x * blockDim.x + threadIdx.x;
    if (e >= E_Q) return;
#pragma unroll
    for (int q = 0; q < 4; q++) {
        int idx = e + q * E_Q;
        if (idx < N_EDGES) {
            int pos = atomicAdd(&g_fill[dst[idx]], 1);
            g_csr_src[pos] = src[idx];
        }
    }
}

// ---------------- bf16 pull aggregation (HADD2 pair-sum, f32x2 accumulate) ----
// agg16[d] = c_in[d] * sum_{s in N(d)} x16[s]   (x16 already carries c_out)
template <int F>
__global__ __launch_bounds__(256)
void pull_bf16_kernel(const __nv_bfloat16* __restrict__ x16) {
    constexpr int LPN = F / 8;                 // lanes per node
    int t = blockIdx.x * blockDim.x + threadIdx.x;
    int node = t / LPN;
    int lane = t % LPN;
    if (node >= N_NODES) return;
    int j = g_rowstart[node];
    int end = g_rowstart[node + 1];
    u64 A0 = 0ull, A1 = 0ull, A2 = 0ull, A3 = 0ull;   // packed f32x2 accumulators
    for (; j + 1 < end; j += 2) {
        int s0 = __ldg(&g_csr_src[j]);
        int s1 = __ldg(&g_csr_src[j + 1]);
        uint4 u0 = __ldg(reinterpret_cast<const uint4*>(x16 + (size_t)s0 * F + lane * 8));
        uint4 u1 = __ldg(reinterpret_cast<const uint4*>(x16 + (size_t)s1 * F + lane * 8));
        acc_f32x2(A0, hadd2u(u0.x, u1.x));
        acc_f32x2(A1, hadd2u(u0.y, u1.y));
        acc_f32x2(A2, hadd2u(u0.z, u1.z));
        acc_f32x2(A3, hadd2u(u0.w, u1.w));
    }
    if (j < end) {
        int s0 = __ldg(&g_csr_src[j]);
        uint4 u0 = __ldg(reinterpret_cast<const uint4*>(x16 + (size_t)s0 * F + lane * 8));
        acc_f32x2(A0, u0.x);
        acc_f32x2(A1, u0.y);
        acc_f32x2(A2, u0.z);
        acc_f32x2(A3, u0.w);
    }
    float ci = __ldg(&g_cin[node]);
    float2 f0 = unpack_f32x2(A0);
    float2 f1 = unpack_f32x2(A1);
    float2 f2 = unpack_f32x2(A2);
    float2 f3 = unpack_f32x2(A3);
    uint4 o;
    o.x = f2bf2(f0.x * ci, f0.y * ci);
    o.y = f2bf2(f1.x * ci, f1.y * ci);
    o.z = f2bf2(f2.x * ci, f2.y * ci);
    o.w = f2bf2(f3.x * ci, f3.y * ci);
    *reinterpret_cast<uint4*>(g_agg16 + (size_t)node * F + lane * 8) = o;
}

// ---------------- tensor-core GEMM (bf16 m16n8k16 mma.sync): -----------------
template <int FIN, bool RELU, bool SCALE_OUT, bool POOL>
__global__ __launch_bounds__(256)
void gemm_tc_kernel(const __nv_bfloat16* __restrict__ A16,
                    const float* __restrict__ W,
                    const float* __restrict__ bias,
                    __nv_bfloat16* __restrict__ C16,
                    const int* __restrict__ gid) {
    extern __shared__ uint32_t smem[];
    constexpr int KPAD = FIN + 8;          // u16 units per A row
    constexpr int NPAD = 136;              // u32 units per W kpair row
    constexpr int NCH = FIN / 32;          // 32-k chunks
    uint16_t* At = reinterpret_cast<uint16_t*>(smem);        // 64 * KPAD u16
    uint32_t* Ws = smem + (64 * KPAD) / 2;                    // 2 * 16 * NPAD u32

    int tid = threadIdx.x;
    int warp = tid >> 5;
    int lane = tid & 31;
    int rowBase = blockIdx.x * 64;

    constexpr int C8 = FIN / 8;            // uint4 chunks per row
    for (int t = tid; t < 64 * C8; t += 256) {
        int row = t / C8;
        int k8 = t % C8;
        int gr = rowBase + row;
        uint4 u = make_uint4(0u, 0u, 0u, 0u);
        if (gr < N_NODES)
            u = __ldg(reinterpret_cast<const uint4*>(A16 + (size_t)gr * FIN + k8 * 8));
        *reinterpret_cast<uint4*>(At + row * KPAD + k8 * 8) = u;
    }
    {
#pragma unroll
        for (int t = 0; t < 4; t++) {
            int p = tid + t * 256;
            int kp = p >> 6;
            int n = (p & 63) * 2;
            float2 lo = __ldg(reinterpret_cast<const float2*>(W + (size_t)(2 * kp) * 128 + n));
            float2 hi = __ldg(reinterpret_cast<const float2*>(W + (size_t)(2 * kp + 1) * 128 + n));
            uint2 st;
            st.x = f2bf2(lo.x, hi.x);
            st.y = f2bf2(lo.y, hi.y);
            *reinterpret_cast<uint2*>(Ws + kp * NPAD + n) = st;
        }
    }
    __syncthreads();

    int m0 = (warp & 3) * 16;
    int n0 = (warp >> 2) * 64;
    int lq = lane & 3;
    int lg = lane >> 2;

    float acc[8][4];
#pragma unroll
    for (int nt = 0; nt < 8; nt++)
#pragma unroll
        for (int j = 0; j < 4; j++) acc[nt][j] = 0.f;

    const uint16_t* arow0 = At + (m0 + lg) * KPAD + 2 * lq;
    const uint16_t* arow1 = arow0 + 8 * KPAD;

#pragma unroll
    for (int ch = 0; ch < NCH; ch++) {
        int cur = ch & 1;
        if (ch + 1 < NCH) {
#pragma unroll
            for (int t = 0; t < 4; t++) {
                int p = tid + t * 256;
                int kp = p >> 6;
                int n = (p & 63) * 2;
                int kg = (ch + 1) * 32 + 2 * kp;
                float2 lo = __ldg(reinterpret_cast<const float2*>(W + (size_t)kg * 128 + n));
                float2 hi = __ldg(reinterpret_cast<const float2*>(W + (size_t)(kg + 1) * 128 + n));
                uint2 st;
                st.x = f2bf2(lo.x, hi.x);
                st.y = f2bf2(lo.y, hi.y);
                *reinterpret_cast<uint2*>(Ws + (cur ^ 1) * 16 * NPAD + kp * NPAD + n) = st;
            }
        }
        const uint32_t* wsb = Ws + cur * 16 * NPAD;
#pragma unroll
        for (int ks = 0; ks < 2; ks++) {
            int kb = ch * 32 + ks * 16;
            uint32_t a0 = *reinterpret_cast<const uint32_t*>(arow0 + kb);
            uint32_t a1 = *reinterpret_cast<const uint32_t*>(arow1 + kb);
            uint32_t a2 = *reinterpret_cast<const uint32_t*>(arow0 + kb + 8);
            uint32_t a3 = *reinterpret_cast<const uint32_t*>(arow1 + kb + 8);
            const uint32_t* b0row = wsb + (ks * 8 + lq) * NPAD + n0 + lg;
            const uint32_t* b1row = b0row + 4 * NPAD;
#pragma unroll
            for (int nt = 0; nt < 8; nt++) {
                uint32_t b0 = b0row[nt * 8];
                uint32_t b1 = b1row[nt * 8];
                mma_bf16(acc[nt][0], acc[nt][1], acc[nt][2], acc[nt][3],
                         a0, a1, a2, a3, b0, b1);
            }
        }
        if (ch + 1 < NCH) __syncthreads();
    }

    int r_lo = rowBase + m0 + lg;
    int r_hi = r_lo + 8;
    float co_lo = 1.f, co_hi = 1.f;
    if (SCALE_OUT) {
        if (r_lo < N_NODES) co_lo = __ldg(&g_cout[r_lo]);
        if (r_hi < N_NODES) co_hi = __ldg(&g_cout[r_hi]);
    }
    int g_lo = 0, g_hi = 0;
    if (POOL) {
        if (r_lo < N_NODES) g_lo = __ldg(&gid[r_lo]);
        if (r_hi < N_NODES) g_hi = __ldg(&gid[r_hi]);
    }
#pragma unroll
    for (int nt = 0; nt < 8; nt++) {
        int col = n0 + nt * 8 + 2 * lq;
        float2 bb = __ldg(reinterpret_cast<const float2*>(bias + col));
        float v0 = acc[nt][0] + bb.x, v1 = acc[nt][1] + bb.y;
        float v2 = acc[nt][2] + bb.x, v3 = acc[nt][3] + bb.y;
        if (RELU) {
            v0 = fmaxf(v0, 0.f); v1 = fmaxf(v1, 0.f);
            v2 = fmaxf(v2, 0.f); v3 = fmaxf(v3, 0.f);
        }
        if (SCALE_OUT) { v0 *= co_lo; v1 *= co_lo; v2 *= co_hi; v3 *= co_hi; }
        if (r_lo < N_NODES) {
            if (POOL) {
                red_add_v2(g_gsum + (size_t)g_lo * 128 + col, v0, v1);
            } else {
                *reinterpret_cast<uint32_t*>(C16 + (size_t)r_lo * 128 + col) = f2bf2(v0, v1);
            }
        }
        if (r_hi < N_NODES) {
            if (POOL) {
                red_add_v2(g_gsum + (size_t)g_hi * 128 + col, v2, v3);
            } else {
                *reinterpret_cast<uint32_t*>(C16 + (size_t)r_hi * 128 + col) = f2bf2(v2, v3);
            }
        }
    }
}

// ---------------- fused MLP head (16 graphs per block) — known-good ----------
__global__ __launch_bounds__(256)
void mlp_kernel(const float* __restrict__ fg,
                const float* __restrict__ Wl1, const float* __restrict__ bl1,
                const float* __restrict__ Wl2, const float* __restrict__ bl2,
                const float* __restrict__ Wl3, const float* __restrict__ bl3,
                float* __restrict__ out) {
    __shared__ float in_s[16][132];
    __shared__ float h_s[16][256];

    int tid = threadIdx.x;
    int gBase = blockIdx.x * 16;

    for (int idx = tid; idx < 16 * 128; idx += 256) {
        int gl = idx >> 7, f = idx & 127;
        int g = gBase + gl;
        float c = (float)g_gcnt[g];
        in_s[gl][f] = g_gsum[(size_t)g * 128 + f] / fmaxf(c, 1.0f);
    }
    for (int idx = tid; idx < 16 * 3; idx += 256) {
        int gl = idx / 3, f = idx % 3;
        in_s[gl][128 + f] = fg[(size_t)(gBase + gl) * 3 + f];
    }
    __syncthreads();

    float acc[16];
    {
        float b = bl1[tid];
#pragma unroll
        for (int g = 0; g < 16; g++) acc[g] = b;
        for (int i = 0; i < 131; i++) {
            float w = __ldg(&Wl1[(size_t)i * 256 + tid]);
#pragma unroll
            for (int g = 0; g < 16; g++) acc[g] = fmaf(in_s[g][i], w, acc[g]);
        }
#pragma unroll
        for (int g = 0; g < 16; g++) h_s[g][tid] = fmaxf(acc[g], 0.f);
    }
    __syncthreads();
    {
        float b = bl2[tid];
#pragma unroll
        for (int g = 0; g < 16; g++) acc[g] = b;
        for (int i = 0; i < 256; i++) {
            float w = __ldg(&Wl2[(size_t)i * 256 + tid]);
#pragma unroll
            for (int g = 0; g < 16; g++) acc[g] = fmaf(h_s[g][i], w, acc[g]);
        }
        __syncthreads();
#pragma unroll
        for (int g = 0; g < 16; g++) h_s[g][tid] = fmaxf(acc[g], 0.f);
    }
    __syncthreads();
    {
        int g = tid >> 4;
        int lane = tid & 15;
        float s = 0.f;
        for (int j = lane; j < 256; j += 16) s += h_s[g][j] * __ldg(&Wl3[j]);
#pragma unroll
        for (int off = 8; off > 0; off >>= 1)
            s += __shfl_down_sync(0xFFFFFFFFu, s, off, 16);
        if (lane == 0) out[gBase + g] = s + bl3[0];
    }
}

// ---------------- launch -----------------------------------------------------
extern "C" void kernel_launch(void* const* d_in, const int* in_sizes, int n_in,
                              void* d_out, int out_size) {
    const float* feats_node  = (const float*)d_in[0];
    const float* feats_graph = (const float*)d_in[1];
    const float* W1 = (const float*)d_in[2];
    const float* b1 = (const float*)d_in[3];
    const float* W2 = (const float*)d_in[4];
    const float* b2 = (const float*)d_in[5];
    const float* W3 = (const float*)d_in[6];
    const float* b3 = (const float*)d_in[7];
    const float* Wl1 = (const float*)d_in[8];
    const float* bl1 = (const float*)d_in[9];
    const float* Wl2 = (const float*)d_in[10];
    const float* bl2 = (const float*)d_in[11];
    const float* Wl3 = (const float*)d_in[12];
    const float* bl3 = (const float*)d_in[13];
    const int* src = (const int*)d_in[14];
    const int* dst = (const int*)d_in[15];
    const int* gid = (const int*)d_in[16];
    float* out = (float*)d_out;

    void *p_agg16, *p_f16, *p_x16, *p_y16;
    cudaGetSymbolAddress(&p_agg16, g_agg16);
    cudaGetSymbolAddress(&p_f16, g_f16);
    cudaGetSymbolAddress(&p_x16, g_x16);
    cudaGetSymbolAddress(&p_y16, g_y16);
    __nv_bfloat16* agg16 = (__nv_bfloat16*)p_agg16;
    __nv_bfloat16* f16 = (__nv_bfloat16*)p_f16;
    __nv_bfloat16* x16 = (__nv_bfloat16*)p_x16;
    __nv_bfloat16* y16 = (__nv_bfloat16*)p_y16;

    const int SMEM64  = 64 * (IN_FEATS + 8) * 2 + 2 * 16 * 136 * 4;   // 26624
    const int SMEM128 = 64 * (HIDDEN + 8) * 2   + 2 * 16 * 136 * 4;   // 34816

    // --- preprocessing: degrees, scan (+coeffs/gcnt/feats->bf16/gsum-zero), fill
    zero_misc_kernel<<<(N_NODES + 255) / 256, 256>>>();
    degree_kernel<<<(E_Q + 255) / 256, 256>>>(src, dst);
    scan_kernel<<<SCAN_NB, SCAN_BS>>>(gid, feats_node);
    fill_kernel<<<(E_Q + 255) / 256, 256>>>(src, dst);

    const int gemm_blocks = (N_NODES + 63) / 64;

    // ---- layer 1 ----
    pull_bf16_kernel<IN_FEATS><<<(N_NODES * (IN_FEATS / 8) + 255) / 256, 256>>>(f16);
    gemm_tc_kernel<IN_FEATS, true, true, false><<<gemm_blocks, 256, SMEM64>>>(agg16, W1, b1, x16, gid);

    // ---- layer 2 ----
    pull_bf16_kernel<HIDDEN><<<(N_NODES * (HIDDEN / 8) + 255) / 256, 256>>>(x16);
    gemm_tc_kernel<HIDDEN, true, true, false><<<gemm_blocks, 256, SMEM128>>>(agg16, W2, b2, y16, gid);

    // ---- layer 3 (+ fused mean-pool RED) ----
    pull_bf16_kernel<HIDDEN><<<(N_NODES * (HIDDEN / 8) + 255) / 256, 256>>>(y16);
    gemm_tc_kernel<HIDDEN, false, false, true><<<gemm_blocks, 256, SMEM128>>>(agg16, W3, b3, nullptr, gid);

    // ---- MLP head ----
    mlp_kernel<<<N_GRAPHS / 16, 256>>>(feats_graph, Wl1, bl1, Wl2, bl2, Wl3, bl3, out);
}

// round 15
// speedup vs baseline: 1.3246x; 1.0164x over previous
#include <cuda_runtime.h>
#include <cuda_bf16.h>
#include <cstdint>

#define N_NODES 50000
#define N_EDGES 600000
#define N_GRAPHS 2000
#define IN_FEATS 64
#define HIDDEN 128
#define SCAN_BS 1024
#define SCAN_NB ((N_NODES + SCAN_BS - 1) / SCAN_BS)   // 49
#define E_Q ((N_EDGES + 3) / 4)

typedef unsigned long long u64;

// ---------------- scratch (device globals; no allocation allowed) ----------
__device__ int   g_deg_out[N_NODES];
__device__ int   g_deg_in[N_NODES];
__device__ float g_cout[N_NODES];
__device__ float g_cin[N_NODES];
__device__ int   g_rowstart[N_NODES + 1];
__device__ int   g_fill[N_NODES];
__device__ int   g_scanagg[SCAN_NB];
__device__ int   g_scanflag[SCAN_NB];
__device__ int   g_csr_src[N_EDGES];
__device__ __nv_bfloat16 g_agg16[(size_t)N_NODES * HIDDEN];  // pull output (bf16)
__device__ __nv_bfloat16 g_f16[(size_t)N_NODES * IN_FEATS];  // feats * c_out
__device__ __nv_bfloat16 g_x16[(size_t)N_NODES * HIDDEN];    // layer1 out * c_out
__device__ __nv_bfloat16 g_y16[(size_t)N_NODES * HIDDEN];    // layer2 out * c_out
__device__ float g_gsum[(size_t)N_GRAPHS * HIDDEN];
__device__ int   g_gcnt[N_GRAPHS];
// pre-packed bf16 k-pair weights: w[ch][kp][n] = {W[ch*32+2kp][n], W[ch*32+2kp+1][n]}
__device__ uint32_t g_w1p[2 * 16 * 128];
__device__ uint32_t g_w2p[4 * 16 * 128];
__device__ uint32_t g_w3p[4 * 16 * 128];

// ---------------- helpers ---------------------------------------------------
__device__ __forceinline__ void red_add_v2(float* p, float x, float y) {
    asm volatile("red.global.add.v2.f32 [%0], {%1, %2};"
                 :: "l"(p), "f"(x), "f"(y) : "memory");
}
__device__ __forceinline__ void mma_bf16(float& d0, float& d1, float& d2, float& d3,
                                         uint32_t a0, uint32_t a1, uint32_t a2, uint32_t a3,
                                         uint32_t b0, uint32_t b1) {
    asm volatile(
        "mma.sync.aligned.m16n8k16.row.col.f32.bf16.bf16.f32 "
        "{%0,%1,%2,%3}, {%4,%5,%6,%7}, {%8,%9}, {%0,%1,%2,%3};"
        : "+f"(d0), "+f"(d1), "+f"(d2), "+f"(d3)
        : "r"(a0), "r"(a1), "r"(a2), "r"(a3), "r"(b0), "r"(b1));
}
__device__ __forceinline__ uint32_t f2bf2(float lo, float hi) {
    __nv_bfloat162 h = __floats2bfloat162_rn(lo, hi);
    return *reinterpret_cast<uint32_t*>(&h);
}
// packed bf16x2 add (HADD2.BF16_V2) on raw u32 carriers
__device__ __forceinline__ uint32_t hadd2u(uint32_t a, uint32_t b) {
    __nv_bfloat162 ha = *reinterpret_cast<__nv_bfloat162*>(&a);
    __nv_bfloat162 hb = *reinterpret_cast<__nv_bfloat162*>(&b);
    __nv_bfloat162 r = __hadd2(ha, hb);
    return *reinterpret_cast<uint32_t*>(&r);
}
// accumulate a bf16x2 pair into a packed f32x2 accumulator (exact expand)
__device__ __forceinline__ void acc_f32x2(u64& acc, uint32_t p) {
    asm("{\n\t"
        ".reg .b32 lo, hi;\n\t"
        ".reg .b64 v;\n\t"
        "shl.b32 lo, %1, 16;\n\t"
        "and.b32 hi, %1, 0xFFFF0000;\n\t"
        "mov.b64 v, {lo, hi};\n\t"
        "add.rn.f32x2 %0, %0, v;\n\t"
        "}" : "+l"(acc) : "r"(p));
}
__device__ __forceinline__ float2 unpack_f32x2(u64 v) {
    float2 f; asm("mov.b64 {%0, %1}, %2;" : "=f"(f.x), "=f"(f.y) : "l"(v)); return f;
}

// ---------------- zero + W pre-pack -------------------------------------------
__global__ void zero_misc_kernel(const float* __restrict__ W1,
                                 const float* __restrict__ W2,
                                 const float* __restrict__ W3) {
    int i = blockIdx.x * blockDim.x + threadIdx.x;
    if (i < N_NODES) { g_deg_out[i] = 0; g_deg_in[i] = 0; }
    if (i < N_GRAPHS) g_gcnt[i] = 0;
    if (i < SCAN_NB) g_scanflag[i] = 0;

    // pack W -> bf16 k-pair u32 (same bytes the GEMM staging produced before)
    // W1: 2 chunks, W2/W3: 4 chunks; each chunk = 16 kp x 128 n
    if (i < 2 * 16 * 128) {
        int kp = i >> 7, n = i & 127;                 // kp = ch*16+kpair
        g_w1p[i] = f2bf2(__ldg(&W1[(size_t)(2 * kp) * 128 + n]),
                         __ldg(&W1[(size_t)(2 * kp + 1) * 128 + n]));
    } else if (i < 2 * 16 * 128 + 4 * 16 * 128) {
        int j = i - 2 * 16 * 128;
        int kp = j >> 7, n = j & 127;
        g_w2p[j] = f2bf2(__ldg(&W2[(size_t)(2 * kp) * 128 + n]),
                         __ldg(&W2[(size_t)(2 * kp + 1) * 128 + n]));
    } else if (i < 2 * 16 * 128 + 8 * 16 * 128) {
        int j = i - 2 * 16 * 128 - 4 * 16 * 128;
        int kp = j >> 7, n = j & 127;
        g_w3p[j] = f2bf2(__ldg(&W3[(size_t)(2 * kp) * 128 + n]),
                         __ldg(&W3[(size_t)(2 * kp + 1) * 128 + n]));
    }
}

__global__ void degree_kernel(const int* __restrict__ src, const int* __restrict__ dst) {
    int e = blockIdx.x * blockDim.x + threadIdx.x;
    if (e >= E_Q) return;
#pragma unroll
    for (int q = 0; q < 4; q++) {
        int idx = e + q * E_Q;
        if (idx < N_EDGES) {
            atomicAdd(&g_deg_out[src[idx]], 1);
            atomicAdd(&g_deg_in[dst[idx]], 1);
        }
    }
}

// ---------------- single-kernel scan (decoupled lookback) + finalize ---------
__global__ __launch_bounds__(SCAN_BS)
void scan_kernel(const int* __restrict__ gid, const float* __restrict__ feats) {
    int b = blockIdx.x;
    int i = b * SCAN_BS + threadIdx.x;
    int lane = threadIdx.x & 31, wid = threadIdx.x >> 5;
    int v = (i < N_NODES) ? g_deg_in[i] : 0;
    int x = v;
#pragma unroll
    for (int o = 1; o < 32; o <<= 1) {
        int y = __shfl_up_sync(0xFFFFFFFFu, x, o);
        if (lane >= o) x += y;
    }
    __shared__ int wsum[32];
    __shared__ int s_prefix;
    if (lane == 31) wsum[wid] = x;
    __syncthreads();
    if (wid == 0) {
        int w = wsum[lane];
#pragma unroll
        for (int o = 1; o < 32; o <<= 1) {
            int y = __shfl_up_sync(0xFFFFFFFFu, w, o);
            if (lane >= o) w += y;
        }
        wsum[lane] = w;
    }
    __syncthreads();
    int excl = x - v + (wid > 0 ? wsum[wid - 1] : 0);

    if (threadIdx.x == 0) {
        g_scanagg[b] = wsum[31];
        __threadfence();
        atomicExch(&g_scanflag[b], 1);
    }
    if (wid == 0) {
        int pre = 0;
        for (int base = 0; base < b; base += 32) {
            int idx = base + lane;
            int val = 0;
            if (idx < b) {
                while (atomicAdd(&g_scanflag[idx], 0) == 0) {}
                val = g_scanagg[idx];
            }
#pragma unroll
            for (int o = 16; o > 0; o >>= 1)
                val += __shfl_xor_sync(0xFFFFFFFFu, val, o);
            pre += val;
        }
        if (lane == 0) s_prefix = pre;
    }
    __syncthreads();
    int prefix = s_prefix;

    if (i < N_NODES) {
        int r = excl + prefix;
        g_rowstart[i] = r;
        g_fill[i] = r;
        g_cout[i] = rsqrtf(fmaxf((float)g_deg_out[i], 1.0f));
        g_cin[i]  = rsqrtf(fmaxf((float)g_deg_in[i], 1.0f));
        atomicAdd(&g_gcnt[gid[i]], 1);
    }
    if (i == 0) g_rowstart[N_NODES] = N_EDGES;
    __syncthreads();   // g_cout for this block's node range now visible

    // convert this block's feats rows to bf16, pre-scaled by c_out (coalesced)
    constexpr int CPN = IN_FEATS / 4;   // float4 chunks per node (16)
    int nodeBase = b * SCAN_BS;
    for (int idx = threadIdx.x; idx < SCAN_BS * CPN; idx += SCAN_BS) {
        int node = nodeBase + idx / CPN;
        int l4 = idx % CPN;
        if (node < N_NODES) {
            float co = g_cout[node];
            float4 fv = __ldg(reinterpret_cast<const float4*>(
                feats + (size_t)node * IN_FEATS + l4 * 4));
            uint2 st;
            st.x = f2bf2(fv.x * co, fv.y * co);
            st.y = f2bf2(fv.z * co, fv.w * co);
            *reinterpret_cast<uint2*>(g_f16 + (size_t)node * IN_FEATS + l4 * 4) = st;
        }
    }

    for (int k = b * SCAN_BS + threadIdx.x; k < N_GRAPHS * HIDDEN; k += SCAN_NB * SCAN_BS)
        g_gsum[k] = 0.0f;
}

__global__ void fill_kernel(const int* __restrict__ src, const int* __restrict__ dst) {
    int e = blockIdx.x * blockDim.x + threadIdx.x;
    if (e >= E_Q) return;
#pragma unroll
    for (int q = 0; q < 4; q++) {
        int idx = e + q * E_Q;
        if (idx < N_EDGES) {
            int pos = atomicAdd(&g_fill[dst[idx]], 1);
            g_csr_src[pos] = src[idx];
        }
    }
}

// ---------------- bf16 pull aggregation (HADD2 pair-sum, f32x2 accumulate) ----
template <int F>
__global__ __launch_bounds__(256)
void pull_bf16_kernel(const __nv_bfloat16* __restrict__ x16) {
    constexpr int LPN = F / 8;                 // lanes per node
    int t = blockIdx.x * blockDim.x + threadIdx.x;
    int node = t / LPN;
    int lane = t % LPN;
    if (node >= N_NODES) return;
    int j = g_rowstart[node];
    int end = g_rowstart[node + 1];
    u64 A0 = 0ull, A1 = 0ull, A2 = 0ull, A3 = 0ull;   // packed f32x2 accumulators
    for (; j + 1 < end; j += 2) {
        int s0 = __ldg(&g_csr_src[j]);
        int s1 = __ldg(&g_csr_src[j + 1]);
        uint4 u0 = __ldg(reinterpret_cast<const uint4*>(x16 + (size_t)s0 * F + lane * 8));
        uint4 u1 = __ldg(reinterpret_cast<const uint4*>(x16 + (size_t)s1 * F + lane * 8));
        acc_f32x2(A0, hadd2u(u0.x, u1.x));
        acc_f32x2(A1, hadd2u(u0.y, u1.y));
        acc_f32x2(A2, hadd2u(u0.z, u1.z));
        acc_f32x2(A3, hadd2u(u0.w, u1.w));
    }
    if (j < end) {
        int s0 = __ldg(&g_csr_src[j]);
        uint4 u0 = __ldg(reinterpret_cast<const uint4*>(x16 + (size_t)s0 * F + lane * 8));
        acc_f32x2(A0, u0.x);
        acc_f32x2(A1, u0.y);
        acc_f32x2(A2, u0.z);
        acc_f32x2(A3, u0.w);
    }
    float ci = __ldg(&g_cin[node]);
    float2 f0 = unpack_f32x2(A0);
    float2 f1 = unpack_f32x2(A1);
    float2 f2 = unpack_f32x2(A2);
    float2 f3 = unpack_f32x2(A3);
    uint4 o;
    o.x = f2bf2(f0.x * ci, f0.y * ci);
    o.y = f2bf2(f1.x * ci, f1.y * ci);
    o.z = f2bf2(f2.x * ci, f2.y * ci);
    o.w = f2bf2(f3.x * ci, f3.y * ci);
    *reinterpret_cast<uint4*>(g_agg16 + (size_t)node * F + lane * 8) = o;
}

// ---------------- tensor-core GEMM (bf16 m16n8k16, pre-packed W) -------------
template <int FIN, bool RELU, bool SCALE_OUT, bool POOL>
__global__ __launch_bounds__(256)
void gemm_tc_kernel(const __nv_bfloat16* __restrict__ A16,
                    const uint32_t* __restrict__ Wp,   // packed bf16 k-pairs
                    const float* __restrict__ bias,
                    __nv_bfloat16* __restrict__ C16,
                    const int* __restrict__ gid) {
    extern __shared__ uint32_t smem[];
    constexpr int KPAD = FIN + 8;          // u16 units per A row
    constexpr int NPAD = 136;              // u32 units per W kpair row
    constexpr int NCH = FIN / 32;          // 32-k chunks
    uint16_t* At = reinterpret_cast<uint16_t*>(smem);        // 64 * KPAD u16
    uint32_t* Ws = smem + (64 * KPAD) / 2;                    // 2 * 16 * NPAD u32

    int tid = threadIdx.x;
    int warp = tid >> 5;
    int lane = tid & 31;
    int rowBase = blockIdx.x * 64;

    constexpr int C8 = FIN / 8;            // uint4 chunks per row
    for (int t = tid; t < 64 * C8; t += 256) {
        int row = t / C8;
        int k8 = t % C8;
        int gr = rowBase + row;
        uint4 u = make_uint4(0u, 0u, 0u, 0u);
        if (gr < N_NODES)
            u = __ldg(reinterpret_cast<const uint4*>(A16 + (size_t)gr * FIN + k8 * 8));
        *reinterpret_cast<uint4*>(At + row * KPAD + k8 * 8) = u;
    }
    // stage W chunk 0: straight uint4 copies of the packed layout
    {
#pragma unroll
        for (int t = 0; t < 2; t++) {
            int p = tid + t * 256;         // 0..511, each handles 4 u32
            int kp = p >> 5;               // (p*4)>>7
            int n4 = (p & 31) * 4;
            uint4 u = __ldg(reinterpret_cast<const uint4*>(Wp + (size_t)kp * 128 + n4));
            *reinterpret_cast<uint4*>(Ws + kp * NPAD + n4) = u;
        }
    }
    __syncthreads();

    int m0 = (warp & 3) * 16;
    int n0 = (warp >> 2) * 64;
    int lq = lane & 3;
    int lg = lane >> 2;

    float acc[8][4];
#pragma unroll
    for (int nt = 0; nt < 8; nt++)
#pragma unroll
        for (int j = 0; j < 4; j++) acc[nt][j] = 0.f;

    const uint16_t* arow0 = At + (m0 + lg) * KPAD + 2 * lq;
    const uint16_t* arow1 = arow0 + 8 * KPAD;

#pragma unroll
    for (int ch = 0; ch < NCH; ch++) {
        int cur = ch & 1;
        if (ch + 1 < NCH) {
#pragma unroll
            for (int t = 0; t < 2; t++) {
                int p = tid + t * 256;
                int kp = p >> 5;
                int n4 = (p & 31) * 4;
                uint4 u = __ldg(reinterpret_cast<const uint4*>(
                    Wp + (size_t)((ch + 1) * 16 + kp) * 128 + n4));
                *reinterpret_cast<uint4*>(Ws + (cur ^ 1) * 16 * NPAD + kp * NPAD + n4) = u;
            }
        }
        const uint32_t* wsb = Ws + cur * 16 * NPAD;
#pragma unroll
        for (int ks = 0; ks < 2; ks++) {
            int kb = ch * 32 + ks * 16;
            uint32_t a0 = *reinterpret_cast<const uint32_t*>(arow0 + kb);
            uint32_t a1 = *reinterpret_cast<const uint32_t*>(arow1 + kb);
            uint32_t a2 = *reinterpret_cast<const uint32_t*>(arow0 + kb + 8);
            uint32_t a3 = *reinterpret_cast<const uint32_t*>(arow1 + kb + 8);
            const uint32_t* b0row = wsb + (ks * 8 + lq) * NPAD + n0 + lg;
            const uint32_t* b1row = b0row + 4 * NPAD;
#pragma unroll
            for (int nt = 0; nt < 8; nt++) {
                uint32_t b0 = b0row[nt * 8];
                uint32_t b1 = b1row[nt * 8];
                mma_bf16(acc[nt][0], acc[nt][1], acc[nt][2], acc[nt][3],
                         a0, a1, a2, a3, b0, b1);
            }
        }
        if (ch + 1 < NCH) __syncthreads();
    }

    int r_lo = rowBase + m0 + lg;
    int r_hi = r_lo + 8;
    float co_lo = 1.f, co_hi = 1.f;
    if (SCALE_OUT) {
        if (r_lo < N_NODES) co_lo = __ldg(&g_cout[r_lo]);
        if (r_hi < N_NODES) co_hi = __ldg(&g_cout[r_hi]);
    }
    int g_lo = 0, g_hi = 0;
    if (POOL) {
        if (r_lo < N_NODES) g_lo = __ldg(&gid[r_lo]);
        if (r_hi < N_NODES) g_hi = __ldg(&gid[r_hi]);
    }
#pragma unroll
    for (int nt = 0; nt < 8; nt++) {
        int col = n0 + nt * 8 + 2 * lq;
        float2 bb = __ldg(reinterpret_cast<const float2*>(bias + col));
        float v0 = acc[nt][0] + bb.x, v1 = acc[nt][1] + bb.y;
        float v2 = acc[nt][2] + bb.x, v3 = acc[nt][3] + bb.y;
        if (RELU) {
            v0 = fmaxf(v0, 0.f); v1 = fmaxf(v1, 0.f);
            v2 = fmaxf(v2, 0.f); v3 = fmaxf(v3, 0.f);
        }
        if (SCALE_OUT) { v0 *= co_lo; v1 *= co_lo; v2 *= co_hi; v3 *= co_hi; }
        if (r_lo < N_NODES) {
            if (POOL) {
                red_add_v2(g_gsum + (size_t)g_lo * 128 + col, v0, v1);
            } else {
                *reinterpret_cast<uint32_t*>(C16 + (size_t)r_lo * 128 + col) = f2bf2(v0, v1);
            }
        }
        if (r_hi < N_NODES) {
            if (POOL) {
                red_add_v2(g_gsum + (size_t)g_hi * 128 + col, v2, v3);
            } else {
                *reinterpret_cast<uint32_t*>(C16 + (size_t)r_hi * 128 + col) = f2bf2(v2, v3);
            }
        }
    }
}

// ---------------- fused MLP head (16 graphs per block) — known-good ----------
__global__ __launch_bounds__(256)
void mlp_kernel(const float* __restrict__ fg,
                const float* __restrict__ Wl1, const float* __restrict__ bl1,
                const float* __restrict__ Wl2, const float* __restrict__ bl2,
                const float* __restrict__ Wl3, const float* __restrict__ bl3,
                float* __restrict__ out) {
    __shared__ float in_s[16][132];
    __shared__ float h_s[16][256];

    int tid = threadIdx.x;
    int gBase = blockIdx.x * 16;

    for (int idx = tid; idx < 16 * 128; idx += 256) {
        int gl = idx >> 7, f = idx & 127;
        int g = gBase + gl;
        float c = (float)g_gcnt[g];
        in_s[gl][f] = g_gsum[(size_t)g * 128 + f] / fmaxf(c, 1.0f);
    }
    for (int idx = tid; idx < 16 * 3; idx += 256) {
        int gl = idx / 3, f = idx % 3;
        in_s[gl][128 + f] = fg[(size_t)(gBase + gl) * 3 + f];
    }
    __syncthreads();

    float acc[16];
    {
        float b = bl1[tid];
#pragma unroll
        for (int g = 0; g < 16; g++) acc[g] = b;
        for (int i = 0; i < 131; i++) {
            float w = __ldg(&Wl1[(size_t)i * 256 + tid]);
#pragma unroll
            for (int g = 0; g < 16; g++) acc[g] = fmaf(in_s[g][i], w, acc[g]);
        }
#pragma unroll
        for (int g = 0; g < 16; g++) h_s[g][tid] = fmaxf(acc[g], 0.f);
    }
    __syncthreads();
    {
        float b = bl2[tid];
#pragma unroll
        for (int g = 0; g < 16; g++) acc[g] = b;
        for (int i = 0; i < 256; i++) {
            float w = __ldg(&Wl2[(size_t)i * 256 + tid]);
#pragma unroll
            for (int g = 0; g < 16; g++) acc[g] = fmaf(h_s[g][i], w, acc[g]);
        }
        __syncthreads();
#pragma unroll
        for (int g = 0; g < 16; g++) h_s[g][tid] = fmaxf(acc[g], 0.f);
    }
    __syncthreads();
    {
        int g = tid >> 4;
        int lane = tid & 15;
        float s = 0.f;
        for (int j = lane; j < 256; j += 16) s += h_s[g][j] * __ldg(&Wl3[j]);
#pragma unroll
        for (int off = 8; off > 0; off >>= 1)
            s += __shfl_down_sync(0xFFFFFFFFu, s, off, 16);
        if (lane == 0) out[gBase + g] = s + bl3[0];
    }
}

// ---------------- launch -----------------------------------------------------
extern "C" void kernel_launch(void* const* d_in, const int* in_sizes, int n_in,
                              void* d_out, int out_size) {
    const float* feats_node  = (const float*)d_in[0];
    const float* feats_graph = (const float*)d_in[1];
    const float* W1 = (const float*)d_in[2];
    const float* b1 = (const float*)d_in[3];
    const float* W2 = (const float*)d_in[4];
    const float* b2 = (const float*)d_in[5];
    const float* W3 = (const float*)d_in[6];
    const float* b3 = (const float*)d_in[7];
    const float* Wl1 = (const float*)d_in[8];
    const float* bl1 = (const float*)d_in[9];
    const float* Wl2 = (const float*)d_in[10];
    const float* bl2 = (const float*)d_in[11];
    const float* Wl3 = (const float*)d_in[12];
    const float* bl3 = (const float*)d_in[13];
    const int* src = (const int*)d_in[14];
    const int* dst = (const int*)d_in[15];
    const int* gid = (const int*)d_in[16];
    float* out = (float*)d_out;

    void *p_agg16, *p_f16, *p_x16, *p_y16, *p_w1p, *p_w2p, *p_w3p;
    cudaGetSymbolAddress(&p_agg16, g_agg16);
    cudaGetSymbolAddress(&p_f16, g_f16);
    cudaGetSymbolAddress(&p_x16, g_x16);
    cudaGetSymbolAddress(&p_y16, g_y16);
    cudaGetSymbolAddress(&p_w1p, g_w1p);
    cudaGetSymbolAddress(&p_w2p, g_w2p);
    cudaGetSymbolAddress(&p_w3p, g_w3p);
    __nv_bfloat16* agg16 = (__nv_bfloat16*)p_agg16;
    __nv_bfloat16* f16 = (__nv_bfloat16*)p_f16;
    __nv_bfloat16* x16 = (__nv_bfloat16*)p_x16;
    __nv_bfloat16* y16 = (__nv_bfloat16*)p_y16;
    const uint32_t* w1p = (const uint32_t*)p_w1p;
    const uint32_t* w2p = (const uint32_t*)p_w2p;
    const uint32_t* w3p = (const uint32_t*)p_w3p;

    const int SMEM64  = 64 * (IN_FEATS + 8) * 2 + 2 * 16 * 136 * 4;   // 26624
    const int SMEM128 = 64 * (HIDDEN + 8) * 2   + 2 * 16 * 136 * 4;   // 34816

    // --- preprocessing: zero+W-pack, degrees, scan(+coeffs/feats), fill ---
    zero_misc_kernel<<<(N_NODES + 255) / 256, 256>>>(W1, W2, W3);
    degree_kernel<<<(E_Q + 255) / 256, 256>>>(src, dst);
    scan_kernel<<<SCAN_NB, SCAN_BS>>>(gid, feats_node);
    fill_kernel<<<(E_Q + 255) / 256, 256>>>(src, dst);

    const int gemm_blocks = (N_NODES + 63) / 64;

    // ---- layer 1 ----
    pull_bf16_kernel<IN_FEATS><<<(N_NODES * (IN_FEATS / 8) + 255) / 256, 256>>>(f16);
    gemm_tc_kernel<IN_FEATS, true, true, false><<<gemm_blocks, 256, SMEM64>>>(agg16, w1p, b1, x16, gid);

    // ---- layer 2 ----
    pull_bf16_kernel<HIDDEN><<<(N_NODES * (HIDDEN / 8) + 255) / 256, 256>>>(x16);
    gemm_tc_kernel<HIDDEN, true, true, false><<<gemm_blocks, 256, SMEM128>>>(agg16, w2p, b2, y16, gid);

    // ---- layer 3 (+ fused mean-pool RED) ----
    pull_bf16_kernel<HIDDEN><<<(N_NODES * (HIDDEN / 8) + 255) / 256, 256>>>(y16);
    gemm_tc_kernel<HIDDEN, false, false, true><<<gemm_blocks, 256, SMEM128>>>(agg16, w3p, b3, nullptr, gid);

    // ---- MLP head ----
    mlp_kernel<<<N_GRAPHS / 16, 256>>>(feats_graph, Wl1, bl1, Wl2, bl2, Wl3, bl3, out);
}

// round 16
// speedup vs baseline: 1.3696x; 1.0340x over previous
#include <cuda_runtime.h>
#include <cuda_bf16.h>
#include <cstdint>

#define N_NODES 50000
#define N_EDGES 600000
#define N_GRAPHS 2000
#define IN_FEATS 64
#define HIDDEN 128
#define SCAN_BS 1024
#define SCAN_NB ((N_NODES + SCAN_BS - 1) / SCAN_BS)   // 49
#define E_Q ((N_EDGES + 3) / 4)
#define FILL_NB ((E_Q + 255) / 256)                    // 586 fill blocks
#define CONV_NB 196                                    // conversion blocks
#define FC_NB (FILL_NB + CONV_NB)

typedef unsigned long long u64;

// ---------------- scratch (device globals; no allocation allowed) ----------
__device__ int   g_deg_out[N_NODES];
__device__ int   g_deg_in[N_NODES];
__device__ float g_cout[N_NODES];
__device__ float g_cin[N_NODES];
__device__ int   g_rowstart[N_NODES + 1];
__device__ int   g_fill[N_NODES];
__device__ int   g_scanagg[SCAN_NB];
__device__ int   g_scanflag[SCAN_NB];
__device__ int   g_csr_src[N_EDGES];
__device__ __nv_bfloat16 g_agg16[(size_t)N_NODES * HIDDEN];  // pull output (bf16)
__device__ __nv_bfloat16 g_f16[(size_t)N_NODES * IN_FEATS];  // feats * c_out
__device__ __nv_bfloat16 g_x16[(size_t)N_NODES * HIDDEN];    // layer1 out * c_out
__device__ __nv_bfloat16 g_y16[(size_t)N_NODES * HIDDEN];    // layer2 out * c_out
__device__ float g_gsum[(size_t)N_GRAPHS * HIDDEN];
__device__ int   g_gcnt[N_GRAPHS];
// pre-packed bf16 k-pair weights: w[ch][kp][n] = {W[ch*32+2kp][n], W[ch*32+2kp+1][n]}
__device__ uint32_t g_w1p[2 * 16 * 128];
__device__ uint32_t g_w2p[4 * 16 * 128];
__device__ uint32_t g_w3p[4 * 16 * 128];

// ---------------- helpers ---------------------------------------------------
__device__ __forceinline__ void red_add_v2(float* p, float x, float y) {
    asm volatile("red.global.add.v2.f32 [%0], {%1, %2};"
                 :: "l"(p), "f"(x), "f"(y) : "memory");
}
__device__ __forceinline__ void mma_bf16(float& d0, float& d1, float& d2, float& d3,
                                         uint32_t a0, uint32_t a1, uint32_t a2, uint32_t a3,
                                         uint32_t b0, uint32_t b1) {
    asm volatile(
        "mma.sync.aligned.m16n8k16.row.col.f32.bf16.bf16.f32 "
        "{%0,%1,%2,%3}, {%4,%5,%6,%7}, {%8,%9}, {%0,%1,%2,%3};"
        : "+f"(d0), "+f"(d1), "+f"(d2), "+f"(d3)
        : "r"(a0), "r"(a1), "r"(a2), "r"(a3), "r"(b0), "r"(b1));
}
__device__ __forceinline__ uint32_t f2bf2(float lo, float hi) {
    __nv_bfloat162 h = __floats2bfloat162_rn(lo, hi);
    return *reinterpret_cast<uint32_t*>(&h);
}
// packed bf16x2 add (HADD2.BF16_V2) on raw u32 carriers
__device__ __forceinline__ uint32_t hadd2u(uint32_t a, uint32_t b) {
    __nv_bfloat162 ha = *reinterpret_cast<__nv_bfloat162*>(&a);
    __nv_bfloat162 hb = *reinterpret_cast<__nv_bfloat162*>(&b);
    __nv_bfloat162 r = __hadd2(ha, hb);
    return *reinterpret_cast<uint32_t*>(&r);
}
// accumulate a bf16x2 pair into a packed f32x2 accumulator (exact expand)
__device__ __forceinline__ void acc_f32x2(u64& acc, uint32_t p) {
    asm("{\n\t"
        ".reg .b32 lo, hi;\n\t"
        ".reg .b64 v;\n\t"
        "shl.b32 lo, %1, 16;\n\t"
        "and.b32 hi, %1, 0xFFFF0000;\n\t"
        "mov.b64 v, {lo, hi};\n\t"
        "add.rn.f32x2 %0, %0, v;\n\t"
        "}" : "+l"(acc) : "r"(p));
}
__device__ __forceinline__ float2 unpack_f32x2(u64 v) {
    float2 f; asm("mov.b64 {%0, %1}, %2;" : "=f"(f.x), "=f"(f.y) : "l"(v)); return f;
}

// ---------------- zero + W pre-pack -------------------------------------------
__global__ void zero_misc_kernel(const float* __restrict__ W1,
                                 const float* __restrict__ W2,
                                 const float* __restrict__ W3) {
    int i = blockIdx.x * blockDim.x + threadIdx.x;
    if (i < N_NODES) { g_deg_out[i] = 0; g_deg_in[i] = 0; }
    if (i < N_GRAPHS) g_gcnt[i] = 0;
    if (i < SCAN_NB) g_scanflag[i] = 0;

    // pack W -> bf16 k-pair u32 (same bytes the GEMM staging produced before)
    if (i < 2 * 16 * 128) {
        int kp = i >> 7, n = i & 127;
        g_w1p[i] = f2bf2(__ldg(&W1[(size_t)(2 * kp) * 128 + n]),
                         __ldg(&W1[(size_t)(2 * kp + 1) * 128 + n]));
    } else if (i < 2 * 16 * 128 + 4 * 16 * 128) {
        int j = i - 2 * 16 * 128;
        int kp = j >> 7, n = j & 127;
        g_w2p[j] = f2bf2(__ldg(&W2[(size_t)(2 * kp) * 128 + n]),
                         __ldg(&W2[(size_t)(2 * kp + 1) * 128 + n]));
    } else if (i < 2 * 16 * 128 + 8 * 16 * 128) {
        int j = i - 2 * 16 * 128 - 4 * 16 * 128;
        int kp = j >> 7, n = j & 127;
        g_w3p[j] = f2bf2(__ldg(&W3[(size_t)(2 * kp) * 128 + n]),
                         __ldg(&W3[(size_t)(2 * kp + 1) * 128 + n]));
    }
}

__global__ void degree_kernel(const int* __restrict__ src, const int* __restrict__ dst) {
    int e = blockIdx.x * blockDim.x + threadIdx.x;
    if (e >= E_Q) return;
#pragma unroll
    for (int q = 0; q < 4; q++) {
        int idx = e + q * E_Q;
        if (idx < N_EDGES) {
            atomicAdd(&g_deg_out[src[idx]], 1);
            atomicAdd(&g_deg_in[dst[idx]], 1);
        }
    }
}

// ---------------- single-kernel scan (decoupled lookback) + coeffs -----------
__global__ __launch_bounds__(SCAN_BS)
void scan_kernel(const int* __restrict__ gid) {
    int b = blockIdx.x;
    int i = b * SCAN_BS + threadIdx.x;
    int lane = threadIdx.x & 31, wid = threadIdx.x >> 5;
    int v = (i < N_NODES) ? g_deg_in[i] : 0;
    int x = v;
#pragma unroll
    for (int o = 1; o < 32; o <<= 1) {
        int y = __shfl_up_sync(0xFFFFFFFFu, x, o);
        if (lane >= o) x += y;
    }
    __shared__ int wsum[32];
    __shared__ int s_prefix;
    if (lane == 31) wsum[wid] = x;
    __syncthreads();
    if (wid == 0) {
        int w = wsum[lane];
#pragma unroll
        for (int o = 1; o < 32; o <<= 1) {
            int y = __shfl_up_sync(0xFFFFFFFFu, w, o);
            if (lane >= o) w += y;
        }
        wsum[lane] = w;
    }
    __syncthreads();
    int excl = x - v + (wid > 0 ? wsum[wid - 1] : 0);

    if (threadIdx.x == 0) {
        g_scanagg[b] = wsum[31];
        __threadfence();
        atomicExch(&g_scanflag[b], 1);
    }
    if (wid == 0) {
        int pre = 0;
        for (int base = 0; base < b; base += 32) {
            int idx = base + lane;
            int val = 0;
            if (idx < b) {
                while (atomicAdd(&g_scanflag[idx], 0) == 0) {}
                val = g_scanagg[idx];
            }
#pragma unroll
            for (int o = 16; o > 0; o >>= 1)
                val += __shfl_xor_sync(0xFFFFFFFFu, val, o);
            pre += val;
        }
        if (lane == 0) s_prefix = pre;
    }
    __syncthreads();
    int prefix = s_prefix;

    if (i < N_NODES) {
        int r = excl + prefix;
        g_rowstart[i] = r;
        g_fill[i] = r;
        g_cout[i] = rsqrtf(fmaxf((float)g_deg_out[i], 1.0f));
        g_cin[i]  = rsqrtf(fmaxf((float)g_deg_in[i], 1.0f));
        atomicAdd(&g_gcnt[gid[i]], 1);
    }
    if (i == 0) g_rowstart[N_NODES] = N_EDGES;
}

// ---------------- fill + feats-conv combined (independent block ranges) ------
// Blocks [0, FILL_NB): CSR fill (4-ILP). Blocks [FILL_NB, FC_NB): feats->bf16
// conversion pre-scaled by c_out, plus gsum zeroing. Both depend only on scan.
__global__ __launch_bounds__(256)
void fill_conv_kernel(const int* __restrict__ src, const int* __restrict__ dst,
                      const float* __restrict__ feats) {
    if (blockIdx.x < FILL_NB) {
        int e = blockIdx.x * 256 + threadIdx.x;
        if (e >= E_Q) return;
#pragma unroll
        for (int q = 0; q < 4; q++) {
            int idx = e + q * E_Q;
            if (idx < N_EDGES) {
                int pos = atomicAdd(&g_fill[dst[idx]], 1);
                g_csr_src[pos] = src[idx];
            }
        }
    } else {
        int t = (blockIdx.x - FILL_NB) * 256 + threadIdx.x;
        const int NT = CONV_NB * 256;
        constexpr int CPN = IN_FEATS / 4;   // float4 chunks per node (16)
        for (int idx = t; idx < N_NODES * CPN; idx += NT) {
            int node = idx / CPN;
            int l4 = idx % CPN;
            float co = g_cout[node];
            float4 fv = __ldg(reinterpret_cast<const float4*>(
                feats + (size_t)node * IN_FEATS + l4 * 4));
            uint2 st;
            st.x = f2bf2(fv.x * co, fv.y * co);
            st.y = f2bf2(fv.z * co, fv.w * co);
            *reinterpret_cast<uint2*>(g_f16 + (size_t)node * IN_FEATS + l4 * 4) = st;
        }
        for (int k = t; k < N_GRAPHS * HIDDEN; k += NT)
            g_gsum[k] = 0.0f;
    }
}

// ---------------- bf16 pull aggregation (HADD2 pair-sum, f32x2 accumulate) ----
template <int F>
__global__ __launch_bounds__(256)
void pull_bf16_kernel(const __nv_bfloat16* __restrict__ x16) {
    constexpr int LPN = F / 8;                 // lanes per node
    int t = blockIdx.x * blockDim.x + threadIdx.x;
    int node = t / LPN;
    int lane = t % LPN;
    if (node >= N_NODES) return;
    int j = g_rowstart[node];
    int end = g_rowstart[node + 1];
    u64 A0 = 0ull, A1 = 0ull, A2 = 0ull, A3 = 0ull;   // packed f32x2 accumulators
    for (; j + 1 < end; j += 2) {
        int s0 = __ldg(&g_csr_src[j]);
        int s1 = __ldg(&g_csr_src[j + 1]);
        uint4 u0 = __ldg(reinterpret_cast<const uint4*>(x16 + (size_t)s0 * F + lane * 8));
        uint4 u1 = __ldg(reinterpret_cast<const uint4*>(x16 + (size_t)s1 * F + lane * 8));
        acc_f32x2(A0, hadd2u(u0.x, u1.x));
        acc_f32x2(A1, hadd2u(u0.y, u1.y));
        acc_f32x2(A2, hadd2u(u0.z, u1.z));
        acc_f32x2(A3, hadd2u(u0.w, u1.w));
    }
    if (j < end) {
        int s0 = __ldg(&g_csr_src[j]);
        uint4 u0 = __ldg(reinterpret_cast<const uint4*>(x16 + (size_t)s0 * F + lane * 8));
        acc_f32x2(A0, u0.x);
        acc_f32x2(A1, u0.y);
        acc_f32x2(A2, u0.z);
        acc_f32x2(A3, u0.w);
    }
    float ci = __ldg(&g_cin[node]);
    float2 f0 = unpack_f32x2(A0);
    float2 f1 = unpack_f32x2(A1);
    float2 f2 = unpack_f32x2(A2);
    float2 f3 = unpack_f32x2(A3);
    uint4 o;
    o.x = f2bf2(f0.x * ci, f0.y * ci);
    o.y = f2bf2(f1.x * ci, f1.y * ci);
    o.z = f2bf2(f2.x * ci, f2.y * ci);
    o.w = f2bf2(f3.x * ci, f3.y * ci);
    *reinterpret_cast<uint4*>(g_agg16 + (size_t)node * F + lane * 8) = o;
}

// ---------------- tensor-core GEMM (bf16 m16n8k16, pre-packed W) -------------
template <int FIN, bool RELU, bool SCALE_OUT, bool POOL>
__global__ __launch_bounds__(256)
void gemm_tc_kernel(const __nv_bfloat16* __restrict__ A16,
                    const uint32_t* __restrict__ Wp,   // packed bf16 k-pairs
                    const float* __restrict__ bias,
                    __nv_bfloat16* __restrict__ C16,
                    const int* __restrict__ gid) {
    extern __shared__ uint32_t smem[];
    constexpr int KPAD = FIN + 8;          // u16 units per A row
    constexpr int NPAD = 136;              // u32 units per W kpair row
    constexpr int NCH = FIN / 32;          // 32-k chunks
    uint16_t* At = reinterpret_cast<uint16_t*>(smem);        // 64 * KPAD u16
    uint32_t* Ws = smem + (64 * KPAD) / 2;                    // 2 * 16 * NPAD u32

    int tid = threadIdx.x;
    int warp = tid >> 5;
    int lane = tid & 31;
    int rowBase = blockIdx.x * 64;

    constexpr int C8 = FIN / 8;            // uint4 chunks per row
    for (int t = tid; t < 64 * C8; t += 256) {
        int row = t / C8;
        int k8 = t % C8;
        int gr = rowBase + row;
        uint4 u = make_uint4(0u, 0u, 0u, 0u);
        if (gr < N_NODES)
            u = __ldg(reinterpret_cast<const uint4*>(A16 + (size_t)gr * FIN + k8 * 8));
        *reinterpret_cast<uint4*>(At + row * KPAD + k8 * 8) = u;
    }
    {
#pragma unroll
        for (int t = 0; t < 2; t++) {
            int p = tid + t * 256;
            int kp = p >> 5;
            int n4 = (p & 31) * 4;
            uint4 u = __ldg(reinterpret_cast<const uint4*>(Wp + (size_t)kp * 128 + n4));
            *reinterpret_cast<uint4*>(Ws + kp * NPAD + n4) = u;
        }
    }
    __syncthreads();

    int m0 = (warp & 3) * 16;
    int n0 = (warp >> 2) * 64;
    int lq = lane & 3;
    int lg = lane >> 2;

    float acc[8][4];
#pragma unroll
    for (int nt = 0; nt < 8; nt++)
#pragma unroll
        for (int j = 0; j < 4; j++) acc[nt][j] = 0.f;

    const uint16_t* arow0 = At + (m0 + lg) * KPAD + 2 * lq;
    const uint16_t* arow1 = arow0 + 8 * KPAD;

#pragma unroll
    for (int ch = 0; ch < NCH; ch++) {
        int cur = ch & 1;
        if (ch + 1 < NCH) {
#pragma unroll
            for (int t = 0; t < 2; t++) {
                int p = tid + t * 256;
                int kp = p >> 5;
                int n4 = (p & 31) * 4;
                uint4 u = __ldg(reinterpret_cast<const uint4*>(
                    Wp + (size_t)((ch + 1) * 16 + kp) * 128 + n4));
                *reinterpret_cast<uint4*>(Ws + (cur ^ 1) * 16 * NPAD + kp * NPAD + n4) = u;
            }
        }
        const uint32_t* wsb = Ws + cur * 16 * NPAD;
#pragma unroll
        for (int ks = 0; ks < 2; ks++) {
            int kb = ch * 32 + ks * 16;
            uint32_t a0 = *reinterpret_cast<const uint32_t*>(arow0 + kb);
            uint32_t a1 = *reinterpret_cast<const uint32_t*>(arow1 + kb);
            uint32_t a2 = *reinterpret_cast<const uint32_t*>(arow0 + kb + 8);
            uint32_t a3 = *reinterpret_cast<const uint32_t*>(arow1 + kb + 8);
            const uint32_t* b0row = wsb + (ks * 8 + lq) * NPAD + n0 + lg;
            const uint32_t* b1row = b0row + 4 * NPAD;
#pragma unroll
            for (int nt = 0; nt < 8; nt++) {
                uint32_t b0 = b0row[nt * 8];
                uint32_t b1 = b1row[nt * 8];
                mma_bf16(acc[nt][0], acc[nt][1], acc[nt][2], acc[nt][3],
                         a0, a1, a2, a3, b0, b1);
            }
        }
        if (ch + 1 < NCH) __syncthreads();
    }

    int r_lo = rowBase + m0 + lg;
    int r_hi = r_lo + 8;
    float co_lo = 1.f, co_hi = 1.f;
    if (SCALE_OUT) {
        if (r_lo < N_NODES) co_lo = __ldg(&g_cout[r_lo]);
        if (r_hi < N_NODES) co_hi = __ldg(&g_cout[r_hi]);
    }
    int g_lo = 0, g_hi = 0;
    if (POOL) {
        if (r_lo < N_NODES) g_lo = __ldg(&gid[r_lo]);
        if (r_hi < N_NODES) g_hi = __ldg(&gid[r_hi]);
    }
#pragma unroll
    for (int nt = 0; nt < 8; nt++) {
        int col = n0 + nt * 8 + 2 * lq;
        float2 bb = __ldg(reinterpret_cast<const float2*>(bias + col));
        float v0 = acc[nt][0] + bb.x, v1 = acc[nt][1] + bb.y;
        float v2 = acc[nt][2] + bb.x, v3 = acc[nt][3] + bb.y;
        if (RELU) {
            v0 = fmaxf(v0, 0.f); v1 = fmaxf(v1, 0.f);
            v2 = fmaxf(v2, 0.f); v3 = fmaxf(v3, 0.f);
        }
        if (SCALE_OUT) { v0 *= co_lo; v1 *= co_lo; v2 *= co_hi; v3 *= co_hi; }
        if (r_lo < N_NODES) {
            if (POOL) {
                red_add_v2(g_gsum + (size_t)g_lo * 128 + col, v0, v1);
            } else {
                *reinterpret_cast<uint32_t*>(C16 + (size_t)r_lo * 128 + col) = f2bf2(v0, v1);
            }
        }
        if (r_hi < N_NODES) {
            if (POOL) {
                red_add_v2(g_gsum + (size_t)g_hi * 128 + col, v2, v3);
            } else {
                *reinterpret_cast<uint32_t*>(C16 + (size_t)r_hi * 128 + col) = f2bf2(v2, v3);
            }
        }
    }
}

// ---------------- fused MLP head (16 graphs per block) — known-good ----------
__global__ __launch_bounds__(256)
void mlp_kernel(const float* __restrict__ fg,
                const float* __restrict__ Wl1, const float* __restrict__ bl1,
                const float* __restrict__ Wl2, const float* __restrict__ bl2,
                const float* __restrict__ Wl3, const float* __restrict__ bl3,
                float* __restrict__ out) {
    __shared__ float in_s[16][132];
    __shared__ float h_s[16][256];

    int tid = threadIdx.x;
    int gBase = blockIdx.x * 16;

    for (int idx = tid; idx < 16 * 128; idx += 256) {
        int gl = idx >> 7, f = idx & 127;
        int g = gBase + gl;
        float c = (float)g_gcnt[g];
        in_s[gl][f] = g_gsum[(size_t)g * 128 + f] / fmaxf(c, 1.0f);
    }
    for (int idx = tid; idx < 16 * 3; idx += 256) {
        int gl = idx / 3, f = idx % 3;
        in_s[gl][128 + f] = fg[(size_t)(gBase + gl) * 3 + f];
    }
    __syncthreads();

    float acc[16];
    {
        float b = bl1[tid];
#pragma unroll
        for (int g = 0; g < 16; g++) acc[g] = b;
        for (int i = 0; i < 131; i++) {
            float w = __ldg(&Wl1[(size_t)i * 256 + tid]);
#pragma unroll
            for (int g = 0; g < 16; g++) acc[g] = fmaf(in_s[g][i], w, acc[g]);
        }
#pragma unroll
        for (int g = 0; g < 16; g++) h_s[g][tid] = fmaxf(acc[g], 0.f);
    }
    __syncthreads();
    {
        float b = bl2[tid];
#pragma unroll
        for (int g = 0; g < 16; g++) acc[g] = b;
        for (int i = 0; i < 256; i++) {
            float w = __ldg(&Wl2[(size_t)i * 256 + tid]);
#pragma unroll
            for (int g = 0; g < 16; g++) acc[g] = fmaf(h_s[g][i], w, acc[g]);
        }
        __syncthreads();
#pragma unroll
        for (int g = 0; g < 16; g++) h_s[g][tid] = fmaxf(acc[g], 0.f);
    }
    __syncthreads();
    {
        int g = tid >> 4;
        int lane = tid & 15;
        float s = 0.f;
        for (int j = lane; j < 256; j += 16) s += h_s[g][j] * __ldg(&Wl3[j]);
#pragma unroll
        for (int off = 8; off > 0; off >>= 1)
            s += __shfl_down_sync(0xFFFFFFFFu, s, off, 16);
        if (lane == 0) out[gBase + g] = s + bl3[0];
    }
}

// ---------------- launch -----------------------------------------------------
extern "C" void kernel_launch(void* const* d_in, const int* in_sizes, int n_in,
                              void* d_out, int out_size) {
    const float* feats_node  = (const float*)d_in[0];
    const float* feats_graph = (const float*)d_in[1];
    const float* W1 = (const float*)d_in[2];
    const float* b1 = (const float*)d_in[3];
    const float* W2 = (const float*)d_in[4];
    const float* b2 = (const float*)d_in[5];
    const float* W3 = (const float*)d_in[6];
    const float* b3 = (const float*)d_in[7];
    const float* Wl1 = (const float*)d_in[8];
    const float* bl1 = (const float*)d_in[9];
    const float* Wl2 = (const float*)d_in[10];
    const float* bl2 = (const float*)d_in[11];
    const float* Wl3 = (const float*)d_in[12];
    const float* bl3 = (const float*)d_in[13];
    const int* src = (const int*)d_in[14];
    const int* dst = (const int*)d_in[15];
    const int* gid = (const int*)d_in[16];
    float* out = (float*)d_out;

    void *p_agg16, *p_f16, *p_x16, *p_y16, *p_w1p, *p_w2p, *p_w3p;
    cudaGetSymbolAddress(&p_agg16, g_agg16);
    cudaGetSymbolAddress(&p_f16, g_f16);
    cudaGetSymbolAddress(&p_x16, g_x16);
    cudaGetSymbolAddress(&p_y16, g_y16);
    cudaGetSymbolAddress(&p_w1p, g_w1p);
    cudaGetSymbolAddress(&p_w2p, g_w2p);
    cudaGetSymbolAddress(&p_w3p, g_w3p);
    __nv_bfloat16* agg16 = (__nv_bfloat16*)p_agg16;
    __nv_bfloat16* f16 = (__nv_bfloat16*)p_f16;
    __nv_bfloat16* x16 = (__nv_bfloat16*)p_x16;
    __nv_bfloat16* y16 = (__nv_bfloat16*)p_y16;
    const uint32_t* w1p = (const uint32_t*)p_w1p;
    const uint32_t* w2p = (const uint32_t*)p_w2p;
    const uint32_t* w3p = (const uint32_t*)p_w3p;

    const int SMEM64  = 64 * (IN_FEATS + 8) * 2 + 2 * 16 * 136 * 4;   // 26624
    const int SMEM128 = 64 * (HIDDEN + 8) * 2   + 2 * 16 * 136 * 4;   // 34816

    // --- preprocessing: zero+W-pack, degrees, scan(+coeffs), fill||feats-conv
    zero_misc_kernel<<<(N_NODES + 255) / 256, 256>>>(W1, W2, W3);
    degree_kernel<<<(E_Q + 255) / 256, 256>>>(src, dst);
    scan_kernel<<<SCAN_NB, SCAN_BS>>>(gid);
    fill_conv_kernel<<<FC_NB, 256>>>(src, dst, feats_node);

    const int gemm_blocks = (N_NODES + 63) / 64;

    // ---- layer 1 ----
    pull_bf16_kernel<IN_FEATS><<<(N_NODES * (IN_FEATS / 8) + 255) / 256, 256>>>(f16);
    gemm_tc_kernel<IN_FEATS, true, true, false><<<gemm_blocks, 256, SMEM64>>>(agg16, w1p, b1, x16, gid);

    // ---- layer 2 ----
    pull_bf16_kernel<HIDDEN><<<(N_NODES * (HIDDEN / 8) + 255) / 256, 256>>>(x16);
    gemm_tc_kernel<HIDDEN, true, true, false><<<gemm_blocks, 256, SMEM128>>>(agg16, w2p, b2, y16, gid);

    // ---- layer 3 (+ fused mean-pool RED) ----
    pull_bf16_kernel<HIDDEN><<<(N_NODES * (HIDDEN / 8) + 255) / 256, 256>>>(y16);
    gemm_tc_kernel<HIDDEN, false, false, true><<<gemm_blocks, 256, SMEM128>>>(agg16, w3p, b3, nullptr, gid);

    // ---- MLP head ----
    mlp_kernel<<<N_GRAPHS / 16, 256>>>(feats_graph, Wl1, bl1, Wl2, bl2, Wl3, bl3, out);
}

// round 17
// speedup vs baseline: 1.4156x; 1.0336x over previous
#include <cuda_runtime.h>
#include <cuda_bf16.h>
#include <cstdint>

#define N_NODES 50000
#define N_EDGES 600000
#define N_GRAPHS 2000
#define IN_FEATS 64
#define HIDDEN 128
#define SCAN_BS 1024
#define SCAN_NB ((N_NODES + SCAN_BS - 1) / SCAN_BS)   // 49
#define E_Q ((N_EDGES + 3) / 4)
#define DEG_NB ((E_Q + 255) / 256)                     // 586 degree blocks
#define WP_NB 80                                       // W-pack blocks (20480/256)
#define FILL_NB ((E_Q + 255) / 256)                    // 586 fill blocks
#define CONV_NB 196                                    // conversion blocks
#define FC_NB (FILL_NB + CONV_NB)

typedef unsigned long long u64;

// ---------------- scratch (device globals; zero-initialized at load) --------
// INVARIANT: g_deg_out/g_deg_in/g_scanflag/g_gcnt/g_gsum are ZERO at entry to
// kernel_launch. Each call re-zeroes them after last use, so the invariant
// holds across graph replays (initial state is zero-initialized).
__device__ int   g_deg_out[N_NODES];
__device__ int   g_deg_in[N_NODES];
__device__ float g_cout[N_NODES];
__device__ float g_cin[N_NODES];
__device__ int   g_rowstart[N_NODES + 1];
__device__ int   g_fill[N_NODES];
__device__ int   g_scanagg[SCAN_NB];
__device__ int   g_scanflag[SCAN_NB];
__device__ int   g_csr_src[N_EDGES];
__device__ __nv_bfloat16 g_agg16[(size_t)N_NODES * HIDDEN];  // pull output (bf16)
__device__ __nv_bfloat16 g_f16[(size_t)N_NODES * IN_FEATS];  // feats * c_out
__device__ __nv_bfloat16 g_x16[(size_t)N_NODES * HIDDEN];    // layer1 out * c_out
__device__ __nv_bfloat16 g_y16[(size_t)N_NODES * HIDDEN];    // layer2 out * c_out
__device__ float g_gsum[(size_t)N_GRAPHS * HIDDEN];
__device__ int   g_gcnt[N_GRAPHS];
// pre-packed bf16 k-pair weights: w[ch][kp][n] = {W[ch*32+2kp][n], W[ch*32+2kp+1][n]}
__device__ uint32_t g_w1p[2 * 16 * 128];
__device__ uint32_t g_w2p[4 * 16 * 128];
__device__ uint32_t g_w3p[4 * 16 * 128];

// ---------------- helpers ---------------------------------------------------
__device__ __forceinline__ void red_add_v2(float* p, float x, float y) {
    asm volatile("red.global.add.v2.f32 [%0], {%1, %2};"
                 :: "l"(p), "f"(x), "f"(y) : "memory");
}
__device__ __forceinline__ void mma_bf16(float& d0, float& d1, float& d2, float& d3,
                                         uint32_t a0, uint32_t a1, uint32_t a2, uint32_t a3,
                                         uint32_t b0, uint32_t b1) {
    asm volatile(
        "mma.sync.aligned.m16n8k16.row.col.f32.bf16.bf16.f32 "
        "{%0,%1,%2,%3}, {%4,%5,%6,%7}, {%8,%9}, {%0,%1,%2,%3};"
        : "+f"(d0), "+f"(d1), "+f"(d2), "+f"(d3)
        : "r"(a0), "r"(a1), "r"(a2), "r"(a3), "r"(b0), "r"(b1));
}
__device__ __forceinline__ uint32_t f2bf2(float lo, float hi) {
    __nv_bfloat162 h = __floats2bfloat162_rn(lo, hi);
    return *reinterpret_cast<uint32_t*>(&h);
}
// packed bf16x2 add (HADD2.BF16_V2) on raw u32 carriers
__device__ __forceinline__ uint32_t hadd2u(uint32_t a, uint32_t b) {
    __nv_bfloat162 ha = *reinterpret_cast<__nv_bfloat162*>(&a);
    __nv_bfloat162 hb = *reinterpret_cast<__nv_bfloat162*>(&b);
    __nv_bfloat162 r = __hadd2(ha, hb);
    return *reinterpret_cast<uint32_t*>(&r);
}
// accumulate a bf16x2 pair into a packed f32x2 accumulator (exact expand)
__device__ __forceinline__ void acc_f32x2(u64& acc, uint32_t p) {
    asm("{\n\t"
        ".reg .b32 lo, hi;\n\t"
        ".reg .b64 v;\n\t"
        "shl.b32 lo, %1, 16;\n\t"
        "and.b32 hi, %1, 0xFFFF0000;\n\t"
        "mov.b64 v, {lo, hi};\n\t"
        "add.rn.f32x2 %0, %0, v;\n\t"
        "}" : "+l"(acc) : "r"(p));
}
__device__ __forceinline__ float2 unpack_f32x2(u64 v) {
    float2 f; asm("mov.b64 {%0, %1}, %2;" : "=f"(f.x), "=f"(f.y) : "l"(v)); return f;
}

// ---------------- degree + W pre-pack (independent block ranges) -------------
// Blocks [0, DEG_NB): edge degree counting (deg arrays are zero at entry).
// Blocks [DEG_NB, DEG_NB+WP_NB): pack W1/W2/W3 -> bf16 k-pair u32.
__global__ __launch_bounds__(256)
void degree_wpack_kernel(const int* __restrict__ src, const int* __restrict__ dst,
                         const float* __restrict__ W1, const float* __restrict__ W2,
                         const float* __restrict__ W3) {
    if (blockIdx.x < DEG_NB) {
        int e = blockIdx.x * 256 + threadIdx.x;
        if (e >= E_Q) return;
#pragma unroll
        for (int q = 0; q < 4; q++) {
            int idx = e + q * E_Q;
            if (idx < N_EDGES) {
                atomicAdd(&g_deg_out[src[idx]], 1);
                atomicAdd(&g_deg_in[dst[idx]], 1);
            }
        }
    } else {
        int i = (blockIdx.x - DEG_NB) * 256 + threadIdx.x;   // 0..20479
        if (i < 2 * 16 * 128) {
            int kp = i >> 7, n = i & 127;
            g_w1p[i] = f2bf2(__ldg(&W1[(size_t)(2 * kp) * 128 + n]),
                             __ldg(&W1[(size_t)(2 * kp + 1) * 128 + n]));
        } else if (i < 2 * 16 * 128 + 4 * 16 * 128) {
            int j = i - 2 * 16 * 128;
            int kp = j >> 7, n = j & 127;
            g_w2p[j] = f2bf2(__ldg(&W2[(size_t)(2 * kp) * 128 + n]),
                             __ldg(&W2[(size_t)(2 * kp + 1) * 128 + n]));
        } else if (i < 2 * 16 * 128 + 8 * 16 * 128) {
            int j = i - 2 * 16 * 128 - 4 * 16 * 128;
            int kp = j >> 7, n = j & 127;
            g_w3p[j] = f2bf2(__ldg(&W3[(size_t)(2 * kp) * 128 + n]),
                             __ldg(&W3[(size_t)(2 * kp + 1) * 128 + n]));
        }
    }
}

// ---------------- single-kernel scan (decoupled lookback) + coeffs -----------
__global__ __launch_bounds__(SCAN_BS)
void scan_kernel(const int* __restrict__ gid) {
    int b = blockIdx.x;
    int i = b * SCAN_BS + threadIdx.x;
    int lane = threadIdx.x & 31, wid = threadIdx.x >> 5;
    int v = (i < N_NODES) ? g_deg_in[i] : 0;
    int x = v;
#pragma unroll
    for (int o = 1; o < 32; o <<= 1) {
        int y = __shfl_up_sync(0xFFFFFFFFu, x, o);
        if (lane >= o) x += y;
    }
    __shared__ int wsum[32];
    __shared__ int s_prefix;
    if (lane == 31) wsum[wid] = x;
    __syncthreads();
    if (wid == 0) {
        int w = wsum[lane];
#pragma unroll
        for (int o = 1; o < 32; o <<= 1) {
            int y = __shfl_up_sync(0xFFFFFFFFu, w, o);
            if (lane >= o) w += y;
        }
        wsum[lane] = w;
    }
    __syncthreads();
    int excl = x - v + (wid > 0 ? wsum[wid - 1] : 0);

    if (threadIdx.x == 0) {
        g_scanagg[b] = wsum[31];
        __threadfence();
        atomicExch(&g_scanflag[b], 1);
    }
    if (wid == 0) {
        int pre = 0;
        for (int base = 0; base < b; base += 32) {
            int idx = base + lane;
            int val = 0;
            if (idx < b) {
                while (atomicAdd(&g_scanflag[idx], 0) == 0) {}
                val = g_scanagg[idx];
            }
#pragma unroll
            for (int o = 16; o > 0; o >>= 1)
                val += __shfl_xor_sync(0xFFFFFFFFu, val, o);
            pre += val;
        }
        if (lane == 0) s_prefix = pre;
    }
    __syncthreads();
    int prefix = s_prefix;

    if (i < N_NODES) {
        int r = excl + prefix;
        g_rowstart[i] = r;
        g_fill[i] = r;
        g_cout[i] = rsqrtf(fmaxf((float)g_deg_out[i], 1.0f));
        g_cin[i]  = rsqrtf(fmaxf((float)g_deg_in[i], 1.0f));
        atomicAdd(&g_gcnt[gid[i]], 1);
    }
    if (i == 0) g_rowstart[N_NODES] = N_EDGES;
}

// ---------------- fill + feats-conv + scratch re-zero (block ranges) ---------
// Blocks [0, FILL_NB): CSR fill (4-ILP). Blocks [FILL_NB, FC_NB): feats->bf16
// conversion, gsum zeroing, and re-zero of deg/scanflag (restores invariant).
__global__ __launch_bounds__(256)
void fill_conv_kernel(const int* __restrict__ src, const int* __restrict__ dst,
                      const float* __restrict__ feats) {
    if (blockIdx.x < FILL_NB) {
        int e = blockIdx.x * 256 + threadIdx.x;
        if (e >= E_Q) return;
#pragma unroll
        for (int q = 0; q < 4; q++) {
            int idx = e + q * E_Q;
            if (idx < N_EDGES) {
                int pos = atomicAdd(&g_fill[dst[idx]], 1);
                g_csr_src[pos] = src[idx];
            }
        }
    } else {
        int t = (blockIdx.x - FILL_NB) * 256 + threadIdx.x;
        const int NT = CONV_NB * 256;
        constexpr int CPN = IN_FEATS / 4;   // float4 chunks per node (16)
        for (int idx = t; idx < N_NODES * CPN; idx += NT) {
            int node = idx / CPN;
            int l4 = idx % CPN;
            float co = g_cout[node];
            float4 fv = __ldg(reinterpret_cast<const float4*>(
                feats + (size_t)node * IN_FEATS + l4 * 4));
            uint2 st;
            st.x = f2bf2(fv.x * co, fv.y * co);
            st.y = f2bf2(fv.z * co, fv.w * co);
            *reinterpret_cast<uint2*>(g_f16 + (size_t)node * IN_FEATS + l4 * 4) = st;
        }
        for (int k = t; k < N_GRAPHS * HIDDEN; k += NT)
            g_gsum[k] = 0.0f;
        // re-zero dead scratch for the next replay (deg arrays die after scan)
        for (int k = t; k < N_NODES; k += NT) { g_deg_out[k] = 0; g_deg_in[k] = 0; }
        for (int k = t; k < SCAN_NB; k += NT) g_scanflag[k] = 0;
    }
}

// ---------------- bf16 pull aggregation (HADD2 pair-sum, f32x2 accumulate) ----
template <int F>
__global__ __launch_bounds__(256)
void pull_bf16_kernel(const __nv_bfloat16* __restrict__ x16) {
    constexpr int LPN = F / 8;                 // lanes per node
    int t = blockIdx.x * blockDim.x + threadIdx.x;
    int node = t / LPN;
    int lane = t % LPN;
    if (node >= N_NODES) return;
    int j = g_rowstart[node];
    int end = g_rowstart[node + 1];
    u64 A0 = 0ull, A1 = 0ull, A2 = 0ull, A3 = 0ull;   // packed f32x2 accumulators
    for (; j + 1 < end; j += 2) {
        int s0 = __ldg(&g_csr_src[j]);
        int s1 = __ldg(&g_csr_src[j + 1]);
        uint4 u0 = __ldg(reinterpret_cast<const uint4*>(x16 + (size_t)s0 * F + lane * 8));
        uint4 u1 = __ldg(reinterpret_cast<const uint4*>(x16 + (size_t)s1 * F + lane * 8));
        acc_f32x2(A0, hadd2u(u0.x, u1.x));
        acc_f32x2(A1, hadd2u(u0.y, u1.y));
        acc_f32x2(A2, hadd2u(u0.z, u1.z));
        acc_f32x2(A3, hadd2u(u0.w, u1.w));
    }
    if (j < end) {
        int s0 = __ldg(&g_csr_src[j]);
        uint4 u0 = __ldg(reinterpret_cast<const uint4*>(x16 + (size_t)s0 * F + lane * 8));
        acc_f32x2(A0, u0.x);
        acc_f32x2(A1, u0.y);
        acc_f32x2(A2, u0.z);
        acc_f32x2(A3, u0.w);
    }
    float ci = __ldg(&g_cin[node]);
    float2 f0 = unpack_f32x2(A0);
    float2 f1 = unpack_f32x2(A1);
    float2 f2 = unpack_f32x2(A2);
    float2 f3 = unpack_f32x2(A3);
    uint4 o;
    o.x = f2bf2(f0.x * ci, f0.y * ci);
    o.y = f2bf2(f1.x * ci, f1.y * ci);
    o.z = f2bf2(f2.x * ci, f2.y * ci);
    o.w = f2bf2(f3.x * ci, f3.y * ci);
    *reinterpret_cast<uint4*>(g_agg16 + (size_t)node * F + lane * 8) = o;
}

// ---------------- tensor-core GEMM (bf16 m16n8k16, pre-packed W) -------------
template <int FIN, bool RELU, bool SCALE_OUT, bool POOL>
__global__ __launch_bounds__(256)
void gemm_tc_kernel(const __nv_bfloat16* __restrict__ A16,
                    const uint32_t* __restrict__ Wp,   // packed bf16 k-pairs
                    const float* __restrict__ bias,
                    __nv_bfloat16* __restrict__ C16,
                    const int* __restrict__ gid) {
    extern __shared__ uint32_t smem[];
    constexpr int KPAD = FIN + 8;          // u16 units per A row
    constexpr int NPAD = 136;              // u32 units per W kpair row
    constexpr int NCH = FIN / 32;          // 32-k chunks
    uint16_t* At = reinterpret_cast<uint16_t*>(smem);        // 64 * KPAD u16
    uint32_t* Ws = smem + (64 * KPAD) / 2;                    // 2 * 16 * NPAD u32

    int tid = threadIdx.x;
    int warp = tid >> 5;
    int lane = tid & 31;
    int rowBase = blockIdx.x * 64;

    constexpr int C8 = FIN / 8;            // uint4 chunks per row
    for (int t = tid; t < 64 * C8; t += 256) {
        int row = t / C8;
        int k8 = t % C8;
        int gr = rowBase + row;
        uint4 u = make_uint4(0u, 0u, 0u, 0u);
        if (gr < N_NODES)
            u = __ldg(reinterpret_cast<const uint4*>(A16 + (size_t)gr * FIN + k8 * 8));
        *reinterpret_cast<uint4*>(At + row * KPAD + k8 * 8) = u;
    }
    {
#pragma unroll
        for (int t = 0; t < 2; t++) {
            int p = tid + t * 256;
            int kp = p >> 5;
            int n4 = (p & 31) * 4;
            uint4 u = __ldg(reinterpret_cast<const uint4*>(Wp + (size_t)kp * 128 + n4));
            *reinterpret_cast<uint4*>(Ws + kp * NPAD + n4) = u;
        }
    }
    __syncthreads();

    int m0 = (warp & 3) * 16;
    int n0 = (warp >> 2) * 64;
    int lq = lane & 3;
    int lg = lane >> 2;

    float acc[8][4];
#pragma unroll
    for (int nt = 0; nt < 8; nt++)
#pragma unroll
        for (int j = 0; j < 4; j++) acc[nt][j] = 0.f;

    const uint16_t* arow0 = At + (m0 + lg) * KPAD + 2 * lq;
    const uint16_t* arow1 = arow0 + 8 * KPAD;

#pragma unroll
    for (int ch = 0; ch < NCH; ch++) {
        int cur = ch & 1;
        if (ch + 1 < NCH) {
#pragma unroll
            for (int t = 0; t < 2; t++) {
                int p = tid + t * 256;
                int kp = p >> 5;
                int n4 = (p & 31) * 4;
                uint4 u = __ldg(reinterpret_cast<const uint4*>(
                    Wp + (size_t)((ch + 1) * 16 + kp) * 128 + n4));
                *reinterpret_cast<uint4*>(Ws + (cur ^ 1) * 16 * NPAD + kp * NPAD + n4) = u;
            }
        }
        const uint32_t* wsb = Ws + cur * 16 * NPAD;
#pragma unroll
        for (int ks = 0; ks < 2; ks++) {
            int kb = ch * 32 + ks * 16;
            uint32_t a0 = *reinterpret_cast<const uint32_t*>(arow0 + kb);
            uint32_t a1 = *reinterpret_cast<const uint32_t*>(arow1 + kb);
            uint32_t a2 = *reinterpret_cast<const uint32_t*>(arow0 + kb + 8);
            uint32_t a3 = *reinterpret_cast<const uint32_t*>(arow1 + kb + 8);
            const uint32_t* b0row = wsb + (ks * 8 + lq) * NPAD + n0 + lg;
            const uint32_t* b1row = b0row + 4 * NPAD;
#pragma unroll
            for (int nt = 0; nt < 8; nt++) {
                uint32_t b0 = b0row[nt * 8];
                uint32_t b1 = b1row[nt * 8];
                mma_bf16(acc[nt][0], acc[nt][1], acc[nt][2], acc[nt][3],
                         a0, a1, a2, a3, b0, b1);
            }
        }
        if (ch + 1 < NCH) __syncthreads();
    }

    int r_lo = rowBase + m0 + lg;
    int r_hi = r_lo + 8;
    float co_lo = 1.f, co_hi = 1.f;
    if (SCALE_OUT) {
        if (r_lo < N_NODES) co_lo = __ldg(&g_cout[r_lo]);
        if (r_hi < N_NODES) co_hi = __ldg(&g_cout[r_hi]);
    }
    int g_lo = 0, g_hi = 0;
    if (POOL) {
        if (r_lo < N_NODES) g_lo = __ldg(&gid[r_lo]);
        if (r_hi < N_NODES) g_hi = __ldg(&gid[r_hi]);
    }
#pragma unroll
    for (int nt = 0; nt < 8; nt++) {
        int col = n0 + nt * 8 + 2 * lq;
        float2 bb = __ldg(reinterpret_cast<const float2*>(bias + col));
        float v0 = acc[nt][0] + bb.x, v1 = acc[nt][1] + bb.y;
        float v2 = acc[nt][2] + bb.x, v3 = acc[nt][3] + bb.y;
        if (RELU) {
            v0 = fmaxf(v0, 0.f); v1 = fmaxf(v1, 0.f);
            v2 = fmaxf(v2, 0.f); v3 = fmaxf(v3, 0.f);
        }
        if (SCALE_OUT) { v0 *= co_lo; v1 *= co_lo; v2 *= co_hi; v3 *= co_hi; }
        if (r_lo < N_NODES) {
            if (POOL) {
                red_add_v2(g_gsum + (size_t)g_lo * 128 + col, v0, v1);
            } else {
                *reinterpret_cast<uint32_t*>(C16 + (size_t)r_lo * 128 + col) = f2bf2(v0, v1);
            }
        }
        if (r_hi < N_NODES) {
            if (POOL) {
                red_add_v2(g_gsum + (size_t)g_hi * 128 + col, v2, v3);
            } else {
                *reinterpret_cast<uint32_t*>(C16 + (size_t)r_hi * 128 + col) = f2bf2(v2, v3);
            }
        }
    }
}

// ---------------- fused MLP head (16 graphs per block) -----------------------
// Re-zeroes g_gcnt for its graphs after staging (restores invariant).
__global__ __launch_bounds__(256)
void mlp_kernel(const float* __restrict__ fg,
                const float* __restrict__ Wl1, const float* __restrict__ bl1,
                const float* __restrict__ Wl2, const float* __restrict__ bl2,
                const float* __restrict__ Wl3, const float* __restrict__ bl3,
                float* __restrict__ out) {
    __shared__ float in_s[16][132];
    __shared__ float h_s[16][256];

    int tid = threadIdx.x;
    int gBase = blockIdx.x * 16;

    for (int idx = tid; idx < 16 * 128; idx += 256) {
        int gl = idx >> 7, f = idx & 127;
        int g = gBase + gl;
        float c = (float)g_gcnt[g];
        in_s[gl][f] = g_gsum[(size_t)g * 128 + f] / fmaxf(c, 1.0f);
    }
    for (int idx = tid; idx < 16 * 3; idx += 256) {
        int gl = idx / 3, f = idx % 3;
        in_s[gl][128 + f] = fg[(size_t)(gBase + gl) * 3 + f];
    }
    __syncthreads();
    if (tid < 16) g_gcnt[gBase + tid] = 0;   // re-zero after last read

    float acc[16];
    {
        float b = bl1[tid];
#pragma unroll
        for (int g = 0; g < 16; g++) acc[g] = b;
        for (int i = 0; i < 131; i++) {
            float w = __ldg(&Wl1[(size_t)i * 256 + tid]);
#pragma unroll
            for (int g = 0; g < 16; g++) acc[g] = fmaf(in_s[g][i], w, acc[g]);
        }
#pragma unroll
        for (int g = 0; g < 16; g++) h_s[g][tid] = fmaxf(acc[g], 0.f);
    }
    __syncthreads();
    {
        float b = bl2[tid];
#pragma unroll
        for (int g = 0; g < 16; g++) acc[g] = b;
        for (int i = 0; i < 256; i++) {
            float w = __ldg(&Wl2[(size_t)i * 256 + tid]);
#pragma unroll
            for (int g = 0; g < 16; g++) acc[g] = fmaf(h_s[g][i], w, acc[g]);
        }
        __syncthreads();
#pragma unroll
        for (int g = 0; g < 16; g++) h_s[g][tid] = fmaxf(acc[g], 0.f);
    }
    __syncthreads();
    {
        int g = tid >> 4;
        int lane = tid & 15;
        float s = 0.f;
        for (int j = lane; j < 256; j += 16) s += h_s[g][j] * __ldg(&Wl3[j]);
#pragma unroll
        for (int off = 8; off > 0; off >>= 1)
            s += __shfl_down_sync(0xFFFFFFFFu, s, off, 16);
        if (lane == 0) out[gBase + g] = s + bl3[0];
    }
}

// ---------------- launch -----------------------------------------------------
extern "C" void kernel_launch(void* const* d_in, const int* in_sizes, int n_in,
                              void* d_out, int out_size) {
    const float* feats_node  = (const float*)d_in[0];
    const float* feats_graph = (const float*)d_in[1];
    const float* W1 = (const float*)d_in[2];
    const float* b1 = (const float*)d_in[3];
    const float* W2 = (const float*)d_in[4];
    const float* b2 = (const float*)d_in[5];
    const float* W3 = (const float*)d_in[6];
    const float* b3 = (const float*)d_in[7];
    const float* Wl1 = (const float*)d_in[8];
    const float* bl1 = (const float*)d_in[9];
    const float* Wl2 = (const float*)d_in[10];
    const float* bl2 = (const float*)d_in[11];
    const float* Wl3 = (const float*)d_in[12];
    const float* bl3 = (const float*)d_in[13];
    const int* src = (const int*)d_in[14];
    const int* dst = (const int*)d_in[15];
    const int* gid = (const int*)d_in[16];
    float* out = (float*)d_out;

    void *p_agg16, *p_f16, *p_x16, *p_y16, *p_w1p, *p_w2p, *p_w3p;
    cudaGetSymbolAddress(&p_agg16, g_agg16);
    cudaGetSymbolAddress(&p_f16, g_f16);
    cudaGetSymbolAddress(&p_x16, g_x16);
    cudaGetSymbolAddress(&p_y16, g_y16);
    cudaGetSymbolAddress(&p_w1p, g_w1p);
    cudaGetSymbolAddress(&p_w2p, g_w2p);
    cudaGetSymbolAddress(&p_w3p, g_w3p);
    __nv_bfloat16* agg16 = (__nv_bfloat16*)p_agg16;
    __nv_bfloat16* f16 = (__nv_bfloat16*)p_f16;
    __nv_bfloat16* x16 = (__nv_bfloat16*)p_x16;
    __nv_bfloat16* y16 = (__nv_bfloat16*)p_y16;
    const uint32_t* w1p = (const uint32_t*)p_w1p;
    const uint32_t* w2p = (const uint32_t*)p_w2p;
    const uint32_t* w3p = (const uint32_t*)p_w3p;

    const int SMEM64  = 64 * (IN_FEATS + 8) * 2 + 2 * 16 * 136 * 4;   // 26624
    const int SMEM128 = 64 * (HIDDEN + 8) * 2   + 2 * 16 * 136 * 4;   // 34816

    // --- preprocessing: degree||W-pack, scan(+coeffs), fill||feats-conv+rezero
    degree_wpack_kernel<<<DEG_NB + WP_NB, 256>>>(src, dst, W1, W2, W3);
    scan_kernel<<<SCAN_NB, SCAN_BS>>>(gid);
    fill_conv_kernel<<<FC_NB, 256>>>(src, dst, feats_node);

    const int gemm_blocks = (N_NODES + 63) / 64;

    // ---- layer 1 ----
    pull_bf16_kernel<IN_FEATS><<<(N_NODES * (IN_FEATS / 8) + 255) / 256, 256>>>(f16);
    gemm_tc_kernel<IN_FEATS, true, true, false><<<gemm_blocks, 256, SMEM64>>>(agg16, w1p, b1, x16, gid);

    // ---- layer 2 ----
    pull_bf16_kernel<HIDDEN><<<(N_NODES * (HIDDEN / 8) + 255) / 256, 256>>>(x16);
    gemm_tc_kernel<HIDDEN, true, true, false><<<gemm_blocks, 256, SMEM128>>>(agg16, w2p, b2, y16, gid);

    // ---- layer 3 (+ fused mean-pool RED) ----
    pull_bf16_kernel<HIDDEN><<<(N_NODES * (HIDDEN / 8) + 255) / 256, 256>>>(y16);
    gemm_tc_kernel<HIDDEN, false, false, true><<<gemm_blocks, 256, SMEM128>>>(agg16, w3p, b3, nullptr, gid);

    // ---- MLP head ----
    mlp_kernel<<<N_GRAPHS / 16, 256>>>(feats_graph, Wl1, bl1, Wl2, bl2, Wl3, bl3, out);
}